// round 8
// baseline (speedup 1.0000x reference)
#include <cuda_runtime.h>
#include <cuda_fp16.h>
#include <math.h>
#include <stdint.h>

#define CC 256
#define HWSZ 4096
#define BATCH 4
#define NHEAD 4
#define NBH 16

// -------- scratch (device globals; no allocations allowed) --------
__device__ __half g_ht [(size_t)BATCH * HWSZ * CC];      // normalized input, [b][tok][c] half
__device__ __half g_oh [(size_t)BATCH * HWSZ * CC];      // attention out, [b][tok][c] half
__device__ __half g_qh [(size_t)NBH * HWSZ * 64];        // q: [bh][tok][c] half, *0.125*log2e
__device__ __half g_kh [(size_t)NBH * HWSZ * 64];        // k: [bh][tok][c] half
__device__ __half g_vh [(size_t)NBH * 64 * HWSZ];        // v: [bh][c][tok] half
__device__ __half g_wqkv[768 * 256];                     // fp16 weights
__device__ __half g_wproj[256 * 256];
__device__ float2 g_part[256];                           // per-slice (sum, sumsq)
__device__ float2 g_stats[32];                           // per (b,group) (mean, rstd)

// ============================================================
// helpers (sm_80-baseline PTX only)
// ============================================================
__device__ __forceinline__ uint32_t smem_u32(const void* p) {
    uint32_t a;
    asm("{ .reg .u64 t; cvta.to.shared.u64 t, %1; cvt.u32.u64 %0, t; }" : "=r"(a) : "l"(p));
    return a;
}
__device__ __forceinline__ float ex2f(float x) {
    float r;
    asm("ex2.approx.ftz.f32 %0, %1;" : "=f"(r) : "f"(x));
    return r;
}
__device__ __forceinline__ uint32_t pack_h2(float lo, float hi) {
    uint32_t d;
    asm("cvt.rn.f16x2.f32 %0, %1, %2;" : "=r"(d) : "f"(hi), "f"(lo));
    return d;
}
__device__ __forceinline__ void cp16(uint32_t dst, const void* src) {
    asm volatile("cp.async.cg.shared.global [%0], [%1], 16;" :: "r"(dst), "l"(src) : "memory");
}
#define CP_COMMIT()  asm volatile("cp.async.commit_group;" ::: "memory")
#define CP_WAIT0()   asm volatile("cp.async.wait_group 0;" ::: "memory")

// fp16 m16n8k16, fp32 accum
__device__ __forceinline__ void mma16(float c[4], const uint32_t a_[4], uint32_t b0, uint32_t b1) {
    asm volatile("mma.sync.aligned.m16n8k16.row.col.f32.f16.f16.f32 "
        "{%0,%1,%2,%3}, {%4,%5,%6,%7}, {%8,%9}, {%0,%1,%2,%3};"
        : "+f"(c[0]), "+f"(c[1]), "+f"(c[2]), "+f"(c[3])
        : "r"(a_[0]), "r"(a_[1]), "r"(a_[2]), "r"(a_[3]),
          "r"(b0), "r"(b1));
}

// ============================================================
// Weight conversion fp32 -> fp16 (once per launch; tiny)
// ============================================================
__global__ void convert_w_kernel(const float* __restrict__ qkv_w,
                                 const float* __restrict__ proj_w) {
    int i = blockIdx.x * 256 + threadIdx.x;
    if (i < 768 * 256) g_wqkv[i] = __float2half_rn(qkv_w[i]);
    else               g_wproj[i - 768 * 256] = __float2half_rn(proj_w[i - 768 * 256]);
}

// ============================================================
// GroupNorm, 3 phases
// ============================================================
__global__ void gn_partial_kernel(const float* __restrict__ x) {
    const int bg = blockIdx.x >> 3, sl = blockIdx.x & 7;
    const float* xp = x + (size_t)bg * 131072 + sl * 16384;
    int tid = threadIdx.x;
    float s = 0.f, ss = 0.f;
    #pragma unroll 4
    for (int i = tid * 4; i < 16384; i += 1024) {
        float4 v = *(const float4*)(xp + i);
        s  += v.x + v.y + v.z + v.w;
        ss += v.x * v.x + v.y * v.y + v.z * v.z + v.w * v.w;
    }
    __shared__ float rs[256], rss[256];
    rs[tid] = s; rss[tid] = ss;
    __syncthreads();
    for (int o = 128; o > 0; o >>= 1) {
        if (tid < o) { rs[tid] += rs[tid + o]; rss[tid] += rss[tid + o]; }
        __syncthreads();
    }
    if (tid == 0) g_part[blockIdx.x] = make_float2(rs[0], rss[0]);
}

__global__ void gn_final_kernel() {
    int t = threadIdx.x;
    float s = 0.f, ss = 0.f;
    #pragma unroll
    for (int i = 0; i < 8; i++) { float2 p = g_part[t * 8 + i]; s += p.x; ss += p.y; }
    float mean = s / 131072.f;
    float var  = ss / 131072.f - mean * mean;
    g_stats[t] = make_float2(mean, rsqrtf(var + 1e-5f));
}

__global__ void gn_norm_kernel(const float* __restrict__ x,
                               const float* __restrict__ w,
                               const float* __restrict__ b) {
    __shared__ float tile[32][129];
    const int t0 = blockIdx.x * 128;
    const int bg = blockIdx.y;
    const int bb = bg >> 3, gg = bg & 7;
    const int tid = threadIdx.x;

    const float* xp = x + ((size_t)bb * 256 + gg * 32) * HWSZ + t0;
    #pragma unroll 4
    for (int i = tid; i < 1024; i += 256) {
        int row = i >> 5, c4 = i & 31;
        float4 v = *(const float4*)(xp + (size_t)row * HWSZ + c4 * 4);
        tile[row][c4 * 4 + 0] = v.x;
        tile[row][c4 * 4 + 1] = v.y;
        tile[row][c4 * 4 + 2] = v.z;
        tile[row][c4 * 4 + 3] = v.w;
    }
    float2 st = g_stats[bg];
    __syncthreads();

    const int tok = tid >> 1, seg = tid & 1;
    __half hv[16];
    #pragma unroll
    for (int i = 0; i < 16; i++) {
        int cc = seg * 16 + i;
        int c = gg * 32 + cc;
        float sc = st.y * w[c];
        float of = b[c] - st.x * sc;
        hv[i] = __float2half_rn(tile[cc][tok] * sc + of);
    }
    __half* dst = g_ht + ((size_t)bb * HWSZ + t0 + tok) * 256 + gg * 32 + seg * 16;
    *(uint4*)dst       = *(uint4*)hv;
    *(uint4*)(dst + 8) = *(uint4*)(hv + 8);
}

// ============================================================
// fp16 tensor-core GEMM (unchanged from R7).
// ============================================================
#define LDWH 20
#define TILEW (128 * LDWH)
#define GEMM_SMEM_BYTES (4 * TILEW * 4)
#define QSCALE 0.18033688011112042f

template<int M_TOTAL, bool QKV_MODE>
__global__ void __launch_bounds__(256, 2) gemm_h_kernel(
        const __half* __restrict__ A,
        const __half* __restrict__ Bt,
        const float* __restrict__ bias,
        const float* __restrict__ resid,
        float* __restrict__ out) {
    extern __shared__ uint32_t sw[];
    uint32_t* a_s = sw;
    uint32_t* b_s = sw + 2 * TILEW;
    const uint32_t a_u = smem_u32(a_s);
    const uint32_t b_u = smem_u32(b_s);

    const int tid = threadIdx.x, lane = tid & 31, wid = tid >> 5;
    const int g4 = lane >> 2, t4 = lane & 3;
    const int wm = wid >> 1, wn = wid & 1;
    const int bb = blockIdx.z;
    const int m0 = blockIdx.y * 128;
    const int n0 = blockIdx.x * 128;
    const __half* Bp = Bt + (size_t)bb * HWSZ * 256 + (size_t)n0 * 256;

    float acc[2][8][4];
    #pragma unroll
    for (int mt = 0; mt < 2; mt++)
        #pragma unroll
        for (int nt = 0; nt < 8; nt++)
            #pragma unroll
            for (int i = 0; i < 4; i++) acc[mt][nt][i] = 0.f;

    #pragma unroll 2
    for (int e = tid; e < 512; e += 256) {
        int r = e >> 2, c8 = e & 3;
        cp16(a_u + (r * LDWH + c8 * 4) * 4, A + (size_t)(m0 + r) * 256 + c8 * 8);
    }
    #pragma unroll 2
    for (int e = tid; e < 512; e += 256) {
        int r = e >> 2, c8 = e & 3;
        cp16(b_u + (r * LDWH + c8 * 4) * 4, Bp + (size_t)r * 256 + c8 * 8);
    }
    CP_COMMIT();

    for (int j = 0; j < 8; j++) {
        const int buf = j & 1;
        const uint32_t* at = a_s + buf * TILEW;
        const uint32_t* bt = b_s + buf * TILEW;

        CP_WAIT0();
        __syncthreads();

        if (j < 7) {
            const uint32_t ad = a_u + ((buf ^ 1) * TILEW) * 4;
            const uint32_t bd = b_u + ((buf ^ 1) * TILEW) * 4;
            const int k0 = (j + 1) * 32;
            #pragma unroll 2
            for (int e = tid; e < 512; e += 256) {
                int r = e >> 2, c8 = e & 3;
                cp16(ad + (r * LDWH + c8 * 4) * 4, A + (size_t)(m0 + r) * 256 + k0 + c8 * 8);
            }
            #pragma unroll 2
            for (int e = tid; e < 512; e += 256) {
                int r = e >> 2, c8 = e & 3;
                cp16(bd + (r * LDWH + c8 * 4) * 4, Bp + (size_t)r * 256 + k0 + c8 * 8);
            }
            CP_COMMIT();
        }

        #pragma unroll
        for (int kt = 0; kt < 2; kt++) {
            uint32_t af[2][4];
            #pragma unroll
            for (int mt = 0; mt < 2; mt++) {
                const uint32_t* ap = at + (wm * 32 + mt * 16 + g4) * LDWH + kt * 8 + t4;
                af[mt][0] = ap[0];
                af[mt][1] = ap[8 * LDWH];
                af[mt][2] = ap[4];
                af[mt][3] = ap[8 * LDWH + 4];
            }
            const uint32_t* bp = bt + (wn * 64 + g4) * LDWH + kt * 8 + t4;
            #pragma unroll
            for (int nt = 0; nt < 8; nt++) {
                uint32_t b0 = bp[nt * 8 * LDWH];
                uint32_t b1 = bp[nt * 8 * LDWH + 4];
                mma16(acc[0][nt], af[0], b0, b1);
                mma16(acc[1][nt], af[1], b0, b1);
            }
        }
        __syncthreads();
    }

    #pragma unroll
    for (int mt = 0; mt < 2; mt++) {
        const int r0 = m0 + wm * 32 + mt * 16 + g4;
        const float bv0 = bias[r0], bv1 = bias[r0 + 8];
        #pragma unroll
        for (int nt = 0; nt < 8; nt++) {
            const int tok = n0 + wn * 64 + nt * 8 + 2 * t4;
            float v0 = acc[mt][nt][0] + bv0;
            float v1 = acc[mt][nt][1] + bv0;
            float v2 = acc[mt][nt][2] + bv1;
            float v3 = acc[mt][nt][3] + bv1;
            if (QKV_MODE) {
                if (r0 < 256) {
                    const int bh = bb * NHEAD + (r0 >> 6);
                    const int c0 = r0 & 63;
                    __half* gq = g_qh + ((size_t)bh * HWSZ + tok) * 64;
                    gq[c0]          = __float2half_rn(v0 * QSCALE);
                    gq[64 + c0]     = __float2half_rn(v1 * QSCALE);
                    gq[c0 + 8]      = __float2half_rn(v2 * QSCALE);
                    gq[64 + c0 + 8] = __float2half_rn(v3 * QSCALE);
                } else if (r0 < 512) {
                    const int bh = bb * NHEAD + ((r0 - 256) >> 6);
                    const int c0 = r0 & 63;
                    __half* gk = g_kh + ((size_t)bh * HWSZ + tok) * 64;
                    gk[c0]          = __float2half_rn(v0);
                    gk[64 + c0]     = __float2half_rn(v1);
                    gk[c0 + 8]      = __float2half_rn(v2);
                    gk[64 + c0 + 8] = __float2half_rn(v3);
                } else {
                    const int cl = r0 - 512;
                    const int bh = bb * NHEAD + (cl >> 6);
                    const int ch = cl & 63;
                    __half* gv = g_vh + ((size_t)bh * 64 + ch) * HWSZ + tok;
                    *(__half2*)gv              = __floats2half2_rn(v0, v1);
                    *(__half2*)(gv + 8 * HWSZ) = __floats2half2_rn(v2, v3);
                }
            } else {
                const float* rp = resid + ((size_t)bb * 256 + r0) * HWSZ + tok;
                float* op = out + ((size_t)bb * 256 + r0) * HWSZ + tok;
                float2 ra = *(const float2*)rp;
                float2 rb = *(const float2*)(rp + 8 * HWSZ);
                *(float2*)op              = make_float2(v0 + ra.x, v1 + ra.y);
                *(float2*)(op + 8 * HWSZ) = make_float2(v2 + rb.x, v3 + rb.y);
            }
        }
    }
}

// ============================================================
// fp16 flash attention: 8 warps x 16 query rows; BN=64 key tiles.
// V tile has 8 constant ones-rows -> l computed by the PV mma (col 64).
// smem: K[2][64][36w] + V[2][72][36w] = 39168 B.
// ============================================================
#define LDW 36
#define KSTR (64 * LDW)               // words per K buffer
#define VSTR (72 * LDW)               // words per V buffer (64 data + 8 ones rows)
#define ATTN_SMEM_BYTES ((2 * KSTR + 2 * VSTR) * 4)

__global__ void __launch_bounds__(256, 2) attn_mma_kernel() {
    extern __shared__ uint32_t smw[];
    uint32_t* ks_base = smw;                  // 2 bufs [64 tok][36 words]
    uint32_t* vs_base = smw + 2 * KSTR;       // 2 bufs [72 rows][36 words]

    const int tid = threadIdx.x, lane = tid & 31, wid = tid >> 5;
    const int g4 = lane >> 2, t4 = lane & 3;
    const int bh = blockIdx.y;
    const int bb = bh >> 2, hh = bh & 3;
    const int i0 = blockIdx.x * 128;
    const int wrow = wid * 16;

    const __half* qg = g_qh + (size_t)bh * HWSZ * 64;
    const __half* kg = g_kh + (size_t)bh * HWSZ * 64;
    const __half* vg = g_vh + (size_t)bh * 64 * HWSZ;

    const uint32_t ks_u = smem_u32(ks_base);
    const uint32_t vs_u = smem_u32(vs_base);

    // ones rows (64-71) of both V buffers, written once
    for (int e = tid; e < 2 * 8 * LDW; e += 256) {
        int buf = e / (8 * LDW), i = e % (8 * LDW);
        vs_base[buf * VSTR + 64 * LDW + i] = 0x3C003C00u;   // (1.0h, 1.0h)
    }

    // Q fragments: 16 rows per warp
    uint32_t qf[4][4];
    {
        const __half* qr0 = qg + (size_t)(i0 + wrow + g4) * 64;
        const __half* qr1 = qr0 + 8 * 64;
        #pragma unroll
        for (int kt = 0; kt < 4; kt++) {
            qf[kt][0] = *(const uint32_t*)(qr0 + kt * 16 + 2 * t4);
            qf[kt][1] = *(const uint32_t*)(qr1 + kt * 16 + 2 * t4);
            qf[kt][2] = *(const uint32_t*)(qr0 + kt * 16 + 2 * t4 + 8);
            qf[kt][3] = *(const uint32_t*)(qr1 + kt * 16 + 2 * t4 + 8);
        }
    }

    float of[9][4];
    #pragma unroll
    for (int nt = 0; nt < 9; nt++)
        #pragma unroll
        for (int i = 0; i < 4; i++) of[nt][i] = 0.f;

    // prologue: tile 0 (512 cp16 each for K and V over 256 threads)
    #pragma unroll 2
    for (int e = tid; e < 512; e += 256) {
        int r = e >> 3, c = e & 7;
        cp16(ks_u + (r * LDW) * 4 + c * 16, kg + (size_t)r * 64 + c * 8);
    }
    #pragma unroll 2
    for (int e = tid; e < 512; e += 256) {
        int r = e >> 3, c = e & 7;
        cp16(vs_u + (r * LDW) * 4 + c * 16, vg + (size_t)r * HWSZ + c * 8);
    }
    CP_COMMIT();

    for (int j = 0; j < 64; j++) {
        const int buf = j & 1;
        const uint32_t* kt_s = ks_base + buf * KSTR;
        const uint32_t* vt_s = vs_base + buf * VSTR;

        CP_WAIT0();
        __syncthreads();

        if (j < 63) {
            const uint32_t kd = ks_u + ((buf ^ 1) * KSTR) * 4;
            const uint32_t vd = vs_u + ((buf ^ 1) * VSTR) * 4;
            const __half* kn = kg + (size_t)(j + 1) * 64 * 64;
            const __half* vn = vg + (j + 1) * 64;
            #pragma unroll 2
            for (int e = tid; e < 512; e += 256) {
                int r = e >> 3, c = e & 7;
                cp16(kd + (r * LDW) * 4 + c * 16, kn + (size_t)r * 64 + c * 8);
            }
            #pragma unroll 2
            for (int e = tid; e < 512; e += 256) {
                int r = e >> 3, c = e & 7;
                cp16(vd + (r * LDW) * 4 + c * 16, vn + (size_t)r * HWSZ + c * 8);
            }
            CP_COMMIT();
        }

        // ---- S = Q @ K^T (16 rows x 64 keys per warp) ----
        float sf[8][4];
        #pragma unroll
        for (int nt = 0; nt < 8; nt++)
            #pragma unroll
            for (int i = 0; i < 4; i++) sf[nt][i] = 0.f;

        #pragma unroll
        for (int kt = 0; kt < 4; kt++) {
            const uint32_t* kp = kt_s + g4 * LDW + kt * 8 + t4;
            #pragma unroll
            for (int nt = 0; nt < 8; nt++) {
                uint32_t b0 = kp[nt * 8 * LDW];
                uint32_t b1 = kp[nt * 8 * LDW + 4];
                mma16(sf[nt], qf[kt], b0, b1);
            }
        }

        // ---- softmax (max-free): P = exp2(S), pack into PV A-frags ----
        uint32_t pa[4][4];
        #pragma unroll
        for (int nt = 0; nt < 8; nt++) {
            float p0 = ex2f(sf[nt][0]);
            float p1 = ex2f(sf[nt][1]);
            float p2 = ex2f(sf[nt][2]);
            float p3 = ex2f(sf[nt][3]);
            pa[nt >> 1][(nt & 1) * 2]     = pack_h2(p0, p1);
            pa[nt >> 1][(nt & 1) * 2 + 1] = pack_h2(p2, p3);
        }

        // ---- O += P @ V^T; nt=8 hits the ones rows -> col 64 = row-sum l ----
        #pragma unroll
        for (int kt = 0; kt < 4; kt++) {
            const uint32_t* vp = vt_s + g4 * LDW + kt * 8 + t4;
            #pragma unroll
            for (int nt = 0; nt < 9; nt++) {
                uint32_t b0 = vp[nt * 8 * LDW];
                uint32_t b1 = vp[nt * 8 * LDW + 4];
                mma16(of[nt], pa[kt], b0, b1);
            }
        }
    }

    // ---- l lives in of[8][0]/of[8][2] of lanes with t4==0; broadcast ----
    float l0 = __shfl_sync(0xffffffffu, of[8][0], lane & 28);
    float l1 = __shfl_sync(0xffffffffu, of[8][2], lane & 28);
    float inv0 = 1.f / l0, inv1 = 1.f / l1;

    // O -> g_oh[b][tok][256] half
    {
        int tok = i0 + wrow + g4;
        __half* d0 = g_oh + ((size_t)bb * HWSZ + tok) * 256 + hh * 64;
        __half* d1 = d0 + 8 * 256;
        #pragma unroll
        for (int nt = 0; nt < 8; nt++) {
            int ch = nt * 8 + 2 * t4;
            *(__half2*)(d0 + ch) = __floats2half2_rn(of[nt][0] * inv0, of[nt][1] * inv0);
            *(__half2*)(d1 + ch) = __floats2half2_rn(of[nt][2] * inv1, of[nt][3] * inv1);
        }
    }
}

// ============================================================
extern "C" void kernel_launch(void* const* d_in, const int* in_sizes, int n_in,
                              void* d_out, int out_size) {
    const float* x      = (const float*)d_in[0];
    const float* norm_w = (const float*)d_in[1];
    const float* norm_b = (const float*)d_in[2];
    const float* qkv_w  = (const float*)d_in[3];
    const float* qkv_b  = (const float*)d_in[4];
    const float* proj_w = (const float*)d_in[5];
    const float* proj_b = (const float*)d_in[6];
    float* out = (float*)d_out;

    void *pht, *poh, *pwq, *pwp;
    cudaGetSymbolAddress(&pht, g_ht);
    cudaGetSymbolAddress(&poh, g_oh);
    cudaGetSymbolAddress(&pwq, g_wqkv);
    cudaGetSymbolAddress(&pwp, g_wproj);

    cudaFuncSetAttribute(gemm_h_kernel<768, true>,
                         cudaFuncAttributeMaxDynamicSharedMemorySize, GEMM_SMEM_BYTES);
    cudaFuncSetAttribute(gemm_h_kernel<256, false>,
                         cudaFuncAttributeMaxDynamicSharedMemorySize, GEMM_SMEM_BYTES);
    cudaFuncSetAttribute(attn_mma_kernel,
                         cudaFuncAttributeMaxDynamicSharedMemorySize, ATTN_SMEM_BYTES);

    convert_w_kernel<<<1024, 256>>>(qkv_w, proj_w);
    gn_partial_kernel<<<256, 256>>>(x);
    gn_final_kernel<<<1, 32>>>();
    gn_norm_kernel<<<dim3(HWSZ / 128, 32), 256>>>(x, norm_w, norm_b);

    gemm_h_kernel<768, true><<<dim3(HWSZ / 128, 768 / 128, BATCH), 256, GEMM_SMEM_BYTES>>>(
        (const __half*)pwq, (const __half*)pht, qkv_b, nullptr, nullptr);

    attn_mma_kernel<<<dim3(HWSZ / 128, NBH), 256, ATTN_SMEM_BYTES>>>();

    gemm_h_kernel<256, false><<<dim3(HWSZ / 128, 256 / 128, BATCH), 256, GEMM_SMEM_BYTES>>>(
        (const __half*)pwp, (const __half*)poh, proj_b, x, out);
}

// round 9
// speedup vs baseline: 1.1235x; 1.1235x over previous
#include <cuda_runtime.h>
#include <cuda_fp16.h>
#include <math.h>
#include <stdint.h>

#define CC 256
#define HWSZ 4096
#define BATCH 4
#define NHEAD 4
#define NBH 16

// -------- scratch (device globals; no allocations allowed) --------
__device__ __half g_ht [(size_t)BATCH * HWSZ * CC];      // normalized input, [b][tok][c] half
__device__ __half g_oh [(size_t)BATCH * HWSZ * CC];      // attention out, [b][tok][c] half
__device__ __half g_qh [(size_t)NBH * HWSZ * 64];        // q: [bh][tok][c] half, *0.125*log2e
__device__ __half g_kh [(size_t)NBH * HWSZ * 64];        // k: [bh][tok][c] half
__device__ __half g_vh [(size_t)NBH * 64 * HWSZ];        // v: [bh][c][tok] half
__device__ __half g_wqkv[768 * 256];                     // fp16 weights
__device__ __half g_wproj[256 * 256];
__device__ float2 g_part[256];                           // per-slice (sum, sumsq)
__device__ float2 g_stats[32];                           // per (b,group) (mean, rstd)

// ============================================================
// helpers (sm_80-baseline PTX only)
// ============================================================
__device__ __forceinline__ uint32_t smem_u32(const void* p) {
    uint32_t a;
    asm("{ .reg .u64 t; cvta.to.shared.u64 t, %1; cvt.u32.u64 %0, t; }" : "=r"(a) : "l"(p));
    return a;
}
__device__ __forceinline__ float ex2f(float x) {
    float r;
    asm("ex2.approx.ftz.f32 %0, %1;" : "=f"(r) : "f"(x));
    return r;
}
__device__ __forceinline__ uint32_t pack_h2(float lo, float hi) {
    uint32_t d;
    asm("cvt.rn.f16x2.f32 %0, %1, %2;" : "=r"(d) : "f"(hi), "f"(lo));
    return d;
}
__device__ __forceinline__ void cp16(uint32_t dst, const void* src) {
    asm volatile("cp.async.cg.shared.global [%0], [%1], 16;" :: "r"(dst), "l"(src) : "memory");
}
#define CP_COMMIT()  asm volatile("cp.async.commit_group;" ::: "memory")
#define CP_WAIT0()   asm volatile("cp.async.wait_group 0;" ::: "memory")

__device__ __forceinline__ void ldsm4(uint32_t r[4], uint32_t addr) {
    asm volatile("ldmatrix.sync.aligned.m8n8.x4.shared.b16 {%0,%1,%2,%3}, [%4];"
        : "=r"(r[0]), "=r"(r[1]), "=r"(r[2]), "=r"(r[3]) : "r"(addr));
}

// fp16 m16n8k16, fp32 accum
__device__ __forceinline__ void mma16(float c[4], const uint32_t a_[4], uint32_t b0, uint32_t b1) {
    asm volatile("mma.sync.aligned.m16n8k16.row.col.f32.f16.f16.f32 "
        "{%0,%1,%2,%3}, {%4,%5,%6,%7}, {%8,%9}, {%0,%1,%2,%3};"
        : "+f"(c[0]), "+f"(c[1]), "+f"(c[2]), "+f"(c[3])
        : "r"(a_[0]), "r"(a_[1]), "r"(a_[2]), "r"(a_[3]),
          "r"(b0), "r"(b1));
}

// ============================================================
// Weight conversion fp32 -> fp16 (vectorized; once per launch)
// ============================================================
__global__ void convert_w_kernel(const float* __restrict__ qkv_w,
                                 const float* __restrict__ proj_w) {
    int i = (blockIdx.x * 256 + threadIdx.x) * 4;   // 320 blocks covers 327680 floats
    float4 v;
    __half2 h0, h1;
    if (i < 768 * 256) {
        v = *(const float4*)(qkv_w + i);
        h0 = __floats2half2_rn(v.x, v.y);
        h1 = __floats2half2_rn(v.z, v.w);
        *(__half2*)(g_wqkv + i)     = h0;
        *(__half2*)(g_wqkv + i + 2) = h1;
    } else {
        int k = i - 768 * 256;
        v = *(const float4*)(proj_w + k);
        h0 = __floats2half2_rn(v.x, v.y);
        h1 = __floats2half2_rn(v.z, v.w);
        *(__half2*)(g_wproj + k)     = h0;
        *(__half2*)(g_wproj + k + 2) = h1;
    }
}

// ============================================================
// GroupNorm, 3 phases (unchanged)
// ============================================================
__global__ void gn_partial_kernel(const float* __restrict__ x) {
    const int bg = blockIdx.x >> 3, sl = blockIdx.x & 7;
    const float* xp = x + (size_t)bg * 131072 + sl * 16384;
    int tid = threadIdx.x;
    float s = 0.f, ss = 0.f;
    #pragma unroll 4
    for (int i = tid * 4; i < 16384; i += 1024) {
        float4 v = *(const float4*)(xp + i);
        s  += v.x + v.y + v.z + v.w;
        ss += v.x * v.x + v.y * v.y + v.z * v.z + v.w * v.w;
    }
    __shared__ float rs[256], rss[256];
    rs[tid] = s; rss[tid] = ss;
    __syncthreads();
    for (int o = 128; o > 0; o >>= 1) {
        if (tid < o) { rs[tid] += rs[tid + o]; rss[tid] += rss[tid + o]; }
        __syncthreads();
    }
    if (tid == 0) g_part[blockIdx.x] = make_float2(rs[0], rss[0]);
}

__global__ void gn_final_kernel() {
    int t = threadIdx.x;
    float s = 0.f, ss = 0.f;
    #pragma unroll
    for (int i = 0; i < 8; i++) { float2 p = g_part[t * 8 + i]; s += p.x; ss += p.y; }
    float mean = s / 131072.f;
    float var  = ss / 131072.f - mean * mean;
    g_stats[t] = make_float2(mean, rsqrtf(var + 1e-5f));
}

__global__ void gn_norm_kernel(const float* __restrict__ x,
                               const float* __restrict__ w,
                               const float* __restrict__ b) {
    __shared__ float tile[32][129];
    const int t0 = blockIdx.x * 128;
    const int bg = blockIdx.y;
    const int bb = bg >> 3, gg = bg & 7;
    const int tid = threadIdx.x;

    const float* xp = x + ((size_t)bb * 256 + gg * 32) * HWSZ + t0;
    #pragma unroll 4
    for (int i = tid; i < 1024; i += 256) {
        int row = i >> 5, c4 = i & 31;
        float4 v = *(const float4*)(xp + (size_t)row * HWSZ + c4 * 4);
        tile[row][c4 * 4 + 0] = v.x;
        tile[row][c4 * 4 + 1] = v.y;
        tile[row][c4 * 4 + 2] = v.z;
        tile[row][c4 * 4 + 3] = v.w;
    }
    float2 st = g_stats[bg];
    __syncthreads();

    const int tok = tid >> 1, seg = tid & 1;
    __half hv[16];
    #pragma unroll
    for (int i = 0; i < 16; i++) {
        int cc = seg * 16 + i;
        int c = gg * 32 + cc;
        float sc = st.y * w[c];
        float of = b[c] - st.x * sc;
        hv[i] = __float2half_rn(tile[cc][tok] * sc + of);
    }
    __half* dst = g_ht + ((size_t)bb * HWSZ + t0 + tok) * 256 + gg * 32 + seg * 16;
    *(uint4*)dst       = *(uint4*)hv;
    *(uint4*)(dst + 8) = *(uint4*)(hv + 8);
}

// ============================================================
// fp16 tensor-core GEMM (unchanged from R7, the 282.7us config).
// ============================================================
#define LDWH 20
#define TILEW (128 * LDWH)
#define GEMM_SMEM_BYTES (4 * TILEW * 4)
#define QSCALE 0.18033688011112042f

template<int M_TOTAL, bool QKV_MODE>
__global__ void __launch_bounds__(256, 2) gemm_h_kernel(
        const __half* __restrict__ A,
        const __half* __restrict__ Bt,
        const float* __restrict__ bias,
        const float* __restrict__ resid,
        float* __restrict__ out) {
    extern __shared__ uint32_t sw[];
    uint32_t* a_s = sw;
    uint32_t* b_s = sw + 2 * TILEW;
    const uint32_t a_u = smem_u32(a_s);
    const uint32_t b_u = smem_u32(b_s);

    const int tid = threadIdx.x, lane = tid & 31, wid = tid >> 5;
    const int g4 = lane >> 2, t4 = lane & 3;
    const int wm = wid >> 1, wn = wid & 1;
    const int bb = blockIdx.z;
    const int m0 = blockIdx.y * 128;
    const int n0 = blockIdx.x * 128;
    const __half* Bp = Bt + (size_t)bb * HWSZ * 256 + (size_t)n0 * 256;

    float acc[2][8][4];
    #pragma unroll
    for (int mt = 0; mt < 2; mt++)
        #pragma unroll
        for (int nt = 0; nt < 8; nt++)
            #pragma unroll
            for (int i = 0; i < 4; i++) acc[mt][nt][i] = 0.f;

    #pragma unroll 2
    for (int e = tid; e < 512; e += 256) {
        int r = e >> 2, c8 = e & 3;
        cp16(a_u + (r * LDWH + c8 * 4) * 4, A + (size_t)(m0 + r) * 256 + c8 * 8);
    }
    #pragma unroll 2
    for (int e = tid; e < 512; e += 256) {
        int r = e >> 2, c8 = e & 3;
        cp16(b_u + (r * LDWH + c8 * 4) * 4, Bp + (size_t)r * 256 + c8 * 8);
    }
    CP_COMMIT();

    for (int j = 0; j < 8; j++) {
        const int buf = j & 1;
        const uint32_t* at = a_s + buf * TILEW;
        const uint32_t* bt = b_s + buf * TILEW;

        CP_WAIT0();
        __syncthreads();

        if (j < 7) {
            const uint32_t ad = a_u + ((buf ^ 1) * TILEW) * 4;
            const uint32_t bd = b_u + ((buf ^ 1) * TILEW) * 4;
            const int k0 = (j + 1) * 32;
            #pragma unroll 2
            for (int e = tid; e < 512; e += 256) {
                int r = e >> 2, c8 = e & 3;
                cp16(ad + (r * LDWH + c8 * 4) * 4, A + (size_t)(m0 + r) * 256 + k0 + c8 * 8);
            }
            #pragma unroll 2
            for (int e = tid; e < 512; e += 256) {
                int r = e >> 2, c8 = e & 3;
                cp16(bd + (r * LDWH + c8 * 4) * 4, Bp + (size_t)r * 256 + k0 + c8 * 8);
            }
            CP_COMMIT();
        }

        #pragma unroll
        for (int kt = 0; kt < 2; kt++) {
            uint32_t af[2][4];
            #pragma unroll
            for (int mt = 0; mt < 2; mt++) {
                const uint32_t* ap = at + (wm * 32 + mt * 16 + g4) * LDWH + kt * 8 + t4;
                af[mt][0] = ap[0];
                af[mt][1] = ap[8 * LDWH];
                af[mt][2] = ap[4];
                af[mt][3] = ap[8 * LDWH + 4];
            }
            const uint32_t* bp = bt + (wn * 64 + g4) * LDWH + kt * 8 + t4;
            #pragma unroll
            for (int nt = 0; nt < 8; nt++) {
                uint32_t b0 = bp[nt * 8 * LDWH];
                uint32_t b1 = bp[nt * 8 * LDWH + 4];
                mma16(acc[0][nt], af[0], b0, b1);
                mma16(acc[1][nt], af[1], b0, b1);
            }
        }
        __syncthreads();
    }

    #pragma unroll
    for (int mt = 0; mt < 2; mt++) {
        const int r0 = m0 + wm * 32 + mt * 16 + g4;
        const float bv0 = bias[r0], bv1 = bias[r0 + 8];
        #pragma unroll
        for (int nt = 0; nt < 8; nt++) {
            const int tok = n0 + wn * 64 + nt * 8 + 2 * t4;
            float v0 = acc[mt][nt][0] + bv0;
            float v1 = acc[mt][nt][1] + bv0;
            float v2 = acc[mt][nt][2] + bv1;
            float v3 = acc[mt][nt][3] + bv1;
            if (QKV_MODE) {
                if (r0 < 256) {
                    const int bh = bb * NHEAD + (r0 >> 6);
                    const int c0 = r0 & 63;
                    __half* gq = g_qh + ((size_t)bh * HWSZ + tok) * 64;
                    gq[c0]          = __float2half_rn(v0 * QSCALE);
                    gq[64 + c0]     = __float2half_rn(v1 * QSCALE);
                    gq[c0 + 8]      = __float2half_rn(v2 * QSCALE);
                    gq[64 + c0 + 8] = __float2half_rn(v3 * QSCALE);
                } else if (r0 < 512) {
                    const int bh = bb * NHEAD + ((r0 - 256) >> 6);
                    const int c0 = r0 & 63;
                    __half* gk = g_kh + ((size_t)bh * HWSZ + tok) * 64;
                    gk[c0]          = __float2half_rn(v0);
                    gk[64 + c0]     = __float2half_rn(v1);
                    gk[c0 + 8]      = __float2half_rn(v2);
                    gk[64 + c0 + 8] = __float2half_rn(v3);
                } else {
                    const int cl = r0 - 512;
                    const int bh = bb * NHEAD + (cl >> 6);
                    const int ch = cl & 63;
                    __half* gv = g_vh + ((size_t)bh * 64 + ch) * HWSZ + tok;
                    *(__half2*)gv              = __floats2half2_rn(v0, v1);
                    *(__half2*)(gv + 8 * HWSZ) = __floats2half2_rn(v2, v3);
                }
            } else {
                const float* rp = resid + ((size_t)bb * 256 + r0) * HWSZ + tok;
                float* op = out + ((size_t)bb * 256 + r0) * HWSZ + tok;
                float2 ra = *(const float2*)rp;
                float2 rb = *(const float2*)(rp + 8 * HWSZ);
                *(float2*)op              = make_float2(v0 + ra.x, v1 + ra.y);
                *(float2*)(op + 8 * HWSZ) = make_float2(v2 + rb.x, v3 + rb.y);
            }
        }
    }
}

// ============================================================
// fp16 flash attention: R7 shape (4 warps x 32 query rows, BN=64)
// + ldmatrix B-frags + ones-constant l-MMA (l free, per-lane).
// smem: K[2][64][36w] + V[2][64][36w] = 36864 B.
// ============================================================
#define LDW 36
#define KVW (64 * LDW)
#define ATTN_SMEM_BYTES (4 * KVW * 4)
#define ONE2 0x3C003C00u

__global__ void __launch_bounds__(128) attn_mma_kernel() {
    extern __shared__ uint32_t smw[];
    uint32_t* ks_base = smw;                 // 2 bufs [64 tok][36 words]
    uint32_t* vs_base = smw + 2 * KVW;       // 2 bufs [64 chan][36 words]

    const int tid = threadIdx.x, lane = tid & 31, wid = tid >> 5;
    const int g4 = lane >> 2, t4 = lane & 3;
    const int bh = blockIdx.y;
    const int bb = bh >> 2, hh = bh & 3;
    const int i0 = blockIdx.x * 128;
    const int wrow = wid * 32;

    const __half* qg = g_qh + (size_t)bh * HWSZ * 64;
    const __half* kg = g_kh + (size_t)bh * HWSZ * 64;
    const __half* vg = g_vh + (size_t)bh * 64 * HWSZ;

    const uint32_t ks_u = smem_u32(ks_base);
    const uint32_t vs_u = smem_u32(vs_base);

    // per-lane ldmatrix row address pieces: matrix id m = lane>>3, row r = lane&7
    // matrices per x4: m0=(ntA,k0) m1=(ntA,k8) m2=(ntB,k0) m3=(ntB,k8)
    const int lm_m = lane >> 3;
    const uint32_t lm_row = (uint32_t)(((lm_m >> 1) * 8) + (lane & 7));  // row within nt-pair (0..15)
    const uint32_t lm_kb  = (uint32_t)((lm_m & 1) * 16);                 // byte offset for k-block

    // Q fragments (held all kernel)
    uint32_t qf[2][4][4];
    #pragma unroll
    for (int mt = 0; mt < 2; mt++) {
        const __half* qr0 = qg + (size_t)(i0 + wrow + mt * 16 + g4) * 64;
        const __half* qr1 = qr0 + 8 * 64;
        #pragma unroll
        for (int kt = 0; kt < 4; kt++) {
            qf[mt][kt][0] = *(const uint32_t*)(qr0 + kt * 16 + 2 * t4);
            qf[mt][kt][1] = *(const uint32_t*)(qr1 + kt * 16 + 2 * t4);
            qf[mt][kt][2] = *(const uint32_t*)(qr0 + kt * 16 + 2 * t4 + 8);
            qf[mt][kt][3] = *(const uint32_t*)(qr1 + kt * 16 + 2 * t4 + 8);
        }
    }

    float of[2][9][4];
    #pragma unroll
    for (int mt = 0; mt < 2; mt++)
        #pragma unroll
        for (int nt = 0; nt < 9; nt++)
            #pragma unroll
            for (int i = 0; i < 4; i++) of[mt][nt][i] = 0.f;

    // prologue: tile 0
    #pragma unroll 4
    for (int e = tid; e < 512; e += 128) {
        int r = e >> 3, c = e & 7;
        cp16(ks_u + (r * LDW) * 4 + c * 16, kg + (size_t)r * 64 + c * 8);
    }
    #pragma unroll 4
    for (int e = tid; e < 512; e += 128) {
        int r = e >> 3, c = e & 7;
        cp16(vs_u + (r * LDW) * 4 + c * 16, vg + (size_t)r * HWSZ + c * 8);
    }
    CP_COMMIT();

    for (int j = 0; j < 64; j++) {
        const int buf = j & 1;
        // per-lane ldmatrix base for this buffer (row term folded in)
        const uint32_t klm = ks_u + (buf * KVW + lm_row * LDW) * 4 + lm_kb;
        const uint32_t vlm = vs_u + (buf * KVW + lm_row * LDW) * 4 + lm_kb;

        CP_WAIT0();
        __syncthreads();

        if (j < 63) {
            const uint32_t kd = ks_u + ((buf ^ 1) * KVW) * 4;
            const uint32_t vd = vs_u + ((buf ^ 1) * KVW) * 4;
            const __half* kn = kg + (size_t)(j + 1) * 64 * 64;
            const __half* vn = vg + (j + 1) * 64;
            #pragma unroll 4
            for (int e = tid; e < 512; e += 128) {
                int r = e >> 3, c = e & 7;
                cp16(kd + (r * LDW) * 4 + c * 16, kn + (size_t)r * 64 + c * 8);
            }
            #pragma unroll 4
            for (int e = tid; e < 512; e += 128) {
                int r = e >> 3, c = e & 7;
                cp16(vd + (r * LDW) * 4 + c * 16, vn + (size_t)r * HWSZ + c * 8);
            }
            CP_COMMIT();
        }

        // ---- S = Q @ K^T (ldmatrix x4: two nt's per load) ----
        float sf[2][8][4];
        #pragma unroll
        for (int mt = 0; mt < 2; mt++)
            #pragma unroll
            for (int nt = 0; nt < 8; nt++)
                #pragma unroll
                for (int i = 0; i < 4; i++) sf[mt][nt][i] = 0.f;

        #pragma unroll
        for (int kt = 0; kt < 4; kt++) {
            #pragma unroll
            for (int ntp = 0; ntp < 4; ntp++) {
                uint32_t br[4];
                ldsm4(br, klm + (ntp * 16 * LDW) * 4 + kt * 32);
                mma16(sf[0][2 * ntp],     qf[0][kt], br[0], br[1]);
                mma16(sf[1][2 * ntp],     qf[1][kt], br[0], br[1]);
                mma16(sf[0][2 * ntp + 1], qf[0][kt], br[2], br[3]);
                mma16(sf[1][2 * ntp + 1], qf[1][kt], br[2], br[3]);
            }
        }

        // ---- softmax (max-free): P = exp2(S) packed to PV A-frags ----
        uint32_t pa[2][4][4];
        #pragma unroll
        for (int mt = 0; mt < 2; mt++) {
            #pragma unroll
            for (int nt = 0; nt < 8; nt++) {
                float p0 = ex2f(sf[mt][nt][0]);
                float p1 = ex2f(sf[mt][nt][1]);
                float p2 = ex2f(sf[mt][nt][2]);
                float p3 = ex2f(sf[mt][nt][3]);
                pa[mt][nt >> 1][(nt & 1) * 2]     = pack_h2(p0, p1);
                pa[mt][nt >> 1][(nt & 1) * 2 + 1] = pack_h2(p2, p3);
            }
        }

        // ---- O += P @ V^T; constant-ones B accumulates l into of[mt][8] ----
        #pragma unroll
        for (int kt = 0; kt < 4; kt++) {
            #pragma unroll
            for (int ntp = 0; ntp < 4; ntp++) {
                uint32_t br[4];
                ldsm4(br, vlm + (ntp * 16 * LDW) * 4 + kt * 32);
                mma16(of[0][2 * ntp],     pa[0][kt], br[0], br[1]);
                mma16(of[1][2 * ntp],     pa[1][kt], br[0], br[1]);
                mma16(of[0][2 * ntp + 1], pa[0][kt], br[2], br[3]);
                mma16(of[1][2 * ntp + 1], pa[1][kt], br[2], br[3]);
            }
            mma16(of[0][8], pa[0][kt], ONE2, ONE2);
            mma16(of[1][8], pa[1][kt], ONE2, ONE2);
        }
    }

    // ---- l is per-lane in of[mt][8][0] (row r) and [2] (row r+8) ----
    #pragma unroll
    for (int mt = 0; mt < 2; mt++) {
        float inv0 = 1.f / of[mt][8][0];
        float inv1 = 1.f / of[mt][8][2];
        int tok = i0 + wrow + mt * 16 + g4;
        __half* d0 = g_oh + ((size_t)bb * HWSZ + tok) * 256 + hh * 64;
        __half* d1 = d0 + 8 * 256;
        #pragma unroll
        for (int nt = 0; nt < 8; nt++) {
            int ch = nt * 8 + 2 * t4;
            *(__half2*)(d0 + ch) = __floats2half2_rn(of[mt][nt][0] * inv0,
                                                     of[mt][nt][1] * inv0);
            *(__half2*)(d1 + ch) = __floats2half2_rn(of[mt][nt][2] * inv1,
                                                     of[mt][nt][3] * inv1);
        }
    }
}

// ============================================================
extern "C" void kernel_launch(void* const* d_in, const int* in_sizes, int n_in,
                              void* d_out, int out_size) {
    const float* x      = (const float*)d_in[0];
    const float* norm_w = (const float*)d_in[1];
    const float* norm_b = (const float*)d_in[2];
    const float* qkv_w  = (const float*)d_in[3];
    const float* qkv_b  = (const float*)d_in[4];
    const float* proj_w = (const float*)d_in[5];
    const float* proj_b = (const float*)d_in[6];
    float* out = (float*)d_out;

    void *pht, *poh, *pwq, *pwp;
    cudaGetSymbolAddress(&pht, g_ht);
    cudaGetSymbolAddress(&poh, g_oh);
    cudaGetSymbolAddress(&pwq, g_wqkv);
    cudaGetSymbolAddress(&pwp, g_wproj);

    cudaFuncSetAttribute(gemm_h_kernel<768, true>,
                         cudaFuncAttributeMaxDynamicSharedMemorySize, GEMM_SMEM_BYTES);
    cudaFuncSetAttribute(gemm_h_kernel<256, false>,
                         cudaFuncAttributeMaxDynamicSharedMemorySize, GEMM_SMEM_BYTES);
    cudaFuncSetAttribute(attn_mma_kernel,
                         cudaFuncAttributeMaxDynamicSharedMemorySize, ATTN_SMEM_BYTES);

    convert_w_kernel<<<320, 256>>>(qkv_w, proj_w);
    gn_partial_kernel<<<256, 256>>>(x);
    gn_final_kernel<<<1, 32>>>();
    gn_norm_kernel<<<dim3(HWSZ / 128, 32), 256>>>(x, norm_w, norm_b);

    gemm_h_kernel<768, true><<<dim3(HWSZ / 128, 768 / 128, BATCH), 256, GEMM_SMEM_BYTES>>>(
        (const __half*)pwq, (const __half*)pht, qkv_b, nullptr, nullptr);

    attn_mma_kernel<<<dim3(HWSZ / 128, NBH), 128, ATTN_SMEM_BYTES>>>();

    gemm_h_kernel<256, false><<<dim3(HWSZ / 128, 256 / 128, BATCH), 256, GEMM_SMEM_BYTES>>>(
        (const __half*)pwp, (const __half*)poh, proj_b, x, out);
}

// round 10
// speedup vs baseline: 1.1308x; 1.0065x over previous
#include <cuda_runtime.h>
#include <cuda_fp16.h>
#include <math.h>
#include <stdint.h>

#define CC 256
#define HWSZ 4096
#define BATCH 4
#define NHEAD 4
#define NBH 16

// -------- scratch (device globals; no allocations allowed) --------
__device__ __half g_ht [(size_t)BATCH * HWSZ * CC];      // normalized input, [b][tok][c] half
__device__ __half g_oh [(size_t)BATCH * HWSZ * CC];      // attention out, [b][tok][c] half
__device__ __half g_qh [(size_t)NBH * HWSZ * 64];        // q: [bh][tok][c] half, *0.125*log2e
__device__ __half g_kh [(size_t)NBH * HWSZ * 64];        // k: [bh][tok][c] half
__device__ __half g_vh [(size_t)NBH * 64 * HWSZ];        // v: [bh][c][tok] half
__device__ __half g_wqkv[768 * 256];                     // fp16 weights
__device__ __half g_wproj[256 * 256];
__device__ float2 g_part[1024];                          // per-slice (sum, sumsq)
__device__ float2 g_stats[32];                           // per (b,group) (mean, rstd)

// ============================================================
// helpers (sm_80-baseline PTX only)
// ============================================================
__device__ __forceinline__ uint32_t smem_u32(const void* p) {
    uint32_t a;
    asm("{ .reg .u64 t; cvta.to.shared.u64 t, %1; cvt.u32.u64 %0, t; }" : "=r"(a) : "l"(p));
    return a;
}
__device__ __forceinline__ float ex2f(float x) {
    float r;
    asm("ex2.approx.ftz.f32 %0, %1;" : "=f"(r) : "f"(x));
    return r;
}
__device__ __forceinline__ uint32_t pack_h2(float lo, float hi) {
    uint32_t d;
    asm("cvt.rn.f16x2.f32 %0, %1, %2;" : "=r"(d) : "f"(hi), "f"(lo));
    return d;
}
__device__ __forceinline__ void cp16(uint32_t dst, const void* src) {
    asm volatile("cp.async.cg.shared.global [%0], [%1], 16;" :: "r"(dst), "l"(src) : "memory");
}
#define CP_COMMIT()  asm volatile("cp.async.commit_group;" ::: "memory")
#define CP_WAIT0()   asm volatile("cp.async.wait_group 0;" ::: "memory")

__device__ __forceinline__ void ldsm4(uint32_t r[4], uint32_t addr) {
    asm volatile("ldmatrix.sync.aligned.m8n8.x4.shared.b16 {%0,%1,%2,%3}, [%4];"
        : "=r"(r[0]), "=r"(r[1]), "=r"(r[2]), "=r"(r[3]) : "r"(addr));
}

// fp16 m16n8k16, fp32 accum
__device__ __forceinline__ void mma16(float c[4], const uint32_t a_[4], uint32_t b0, uint32_t b1) {
    asm volatile("mma.sync.aligned.m16n8k16.row.col.f32.f16.f16.f32 "
        "{%0,%1,%2,%3}, {%4,%5,%6,%7}, {%8,%9}, {%0,%1,%2,%3};"
        : "+f"(c[0]), "+f"(c[1]), "+f"(c[2]), "+f"(c[3])
        : "r"(a_[0]), "r"(a_[1]), "r"(a_[2]), "r"(a_[3]),
          "r"(b0), "r"(b1));
}

// ============================================================
// Weight conversion fp32 -> fp16 (vectorized; once per launch)
// ============================================================
__global__ void convert_w_kernel(const float* __restrict__ qkv_w,
                                 const float* __restrict__ proj_w) {
    int i = (blockIdx.x * 256 + threadIdx.x) * 4;
    float4 v;
    __half2 h0, h1;
    if (i < 768 * 256) {
        v = *(const float4*)(qkv_w + i);
        h0 = __floats2half2_rn(v.x, v.y);
        h1 = __floats2half2_rn(v.z, v.w);
        *(__half2*)(g_wqkv + i)     = h0;
        *(__half2*)(g_wqkv + i + 2) = h1;
    } else {
        int k = i - 768 * 256;
        v = *(const float4*)(proj_w + k);
        h0 = __floats2half2_rn(v.x, v.y);
        h1 = __floats2half2_rn(v.z, v.w);
        *(__half2*)(g_wproj + k)     = h0;
        *(__half2*)(g_wproj + k + 2) = h1;
    }
}

// ============================================================
// GroupNorm, 3 phases
// ============================================================
__global__ void gn_partial_kernel(const float* __restrict__ x) {
    // 1024 blocks x 128 threads; slice = 4096 floats
    const float* xp = x + (size_t)blockIdx.x * 4096;
    int tid = threadIdx.x;
    float s = 0.f, ss = 0.f;
    #pragma unroll 8
    for (int i = tid * 4; i < 4096; i += 512) {
        float4 v = *(const float4*)(xp + i);
        s  += v.x + v.y + v.z + v.w;
        ss += v.x * v.x + v.y * v.y + v.z * v.z + v.w * v.w;
    }
    __shared__ float rs[128], rss[128];
    rs[tid] = s; rss[tid] = ss;
    __syncthreads();
    for (int o = 64; o > 0; o >>= 1) {
        if (tid < o) { rs[tid] += rs[tid + o]; rss[tid] += rss[tid + o]; }
        __syncthreads();
    }
    if (tid == 0) g_part[blockIdx.x] = make_float2(rs[0], rss[0]);
}

__global__ void gn_final_kernel() {
    int t = threadIdx.x;   // 32 threads, one per (b,group); 32 slices each
    float s = 0.f, ss = 0.f;
    #pragma unroll
    for (int i = 0; i < 32; i++) { float2 p = g_part[t * 32 + i]; s += p.x; ss += p.y; }
    float mean = s / 131072.f;
    float var  = ss / 131072.f - mean * mean;
    g_stats[t] = make_float2(mean, rsqrtf(var + 1e-5f));
}

__global__ void gn_norm_kernel(const float* __restrict__ x,
                               const float* __restrict__ w,
                               const float* __restrict__ b) {
    __shared__ float tile[32][129];
    const int t0 = blockIdx.x * 128;
    const int bg = blockIdx.y;
    const int bb = bg >> 3, gg = bg & 7;
    const int tid = threadIdx.x;

    const float* xp = x + ((size_t)bb * 256 + gg * 32) * HWSZ + t0;
    #pragma unroll 4
    for (int i = tid; i < 1024; i += 256) {
        int row = i >> 5, c4 = i & 31;
        float4 v = *(const float4*)(xp + (size_t)row * HWSZ + c4 * 4);
        tile[row][c4 * 4 + 0] = v.x;
        tile[row][c4 * 4 + 1] = v.y;
        tile[row][c4 * 4 + 2] = v.z;
        tile[row][c4 * 4 + 3] = v.w;
    }
    float2 st = g_stats[bg];
    __syncthreads();

    const int tok = tid >> 1, seg = tid & 1;
    __half hv[16];
    #pragma unroll
    for (int i = 0; i < 16; i++) {
        int cc = seg * 16 + i;
        int c = gg * 32 + cc;
        float sc = st.y * w[c];
        float of = b[c] - st.x * sc;
        hv[i] = __float2half_rn(tile[cc][tok] * sc + of);
    }
    __half* dst = g_ht + ((size_t)bb * HWSZ + t0 + tok) * 256 + gg * 32 + seg * 16;
    *(uint4*)dst       = *(uint4*)hv;
    *(uint4*)(dst + 8) = *(uint4*)(hv + 8);
}

// ============================================================
// fp16 tensor-core GEMM (unchanged, proven).
// ============================================================
#define LDWH 20
#define TILEW (128 * LDWH)
#define GEMM_SMEM_BYTES (4 * TILEW * 4)
#define QSCALE 0.18033688011112042f

template<int M_TOTAL, bool QKV_MODE>
__global__ void __launch_bounds__(256, 2) gemm_h_kernel(
        const __half* __restrict__ A,
        const __half* __restrict__ Bt,
        const float* __restrict__ bias,
        const float* __restrict__ resid,
        float* __restrict__ out) {
    extern __shared__ uint32_t sw[];
    uint32_t* a_s = sw;
    uint32_t* b_s = sw + 2 * TILEW;
    const uint32_t a_u = smem_u32(a_s);
    const uint32_t b_u = smem_u32(b_s);

    const int tid = threadIdx.x, lane = tid & 31, wid = tid >> 5;
    const int g4 = lane >> 2, t4 = lane & 3;
    const int wm = wid >> 1, wn = wid & 1;
    const int bb = blockIdx.z;
    const int m0 = blockIdx.y * 128;
    const int n0 = blockIdx.x * 128;
    const __half* Bp = Bt + (size_t)bb * HWSZ * 256 + (size_t)n0 * 256;

    float acc[2][8][4];
    #pragma unroll
    for (int mt = 0; mt < 2; mt++)
        #pragma unroll
        for (int nt = 0; nt < 8; nt++)
            #pragma unroll
            for (int i = 0; i < 4; i++) acc[mt][nt][i] = 0.f;

    #pragma unroll 2
    for (int e = tid; e < 512; e += 256) {
        int r = e >> 2, c8 = e & 3;
        cp16(a_u + (r * LDWH + c8 * 4) * 4, A + (size_t)(m0 + r) * 256 + c8 * 8);
    }
    #pragma unroll 2
    for (int e = tid; e < 512; e += 256) {
        int r = e >> 2, c8 = e & 3;
        cp16(b_u + (r * LDWH + c8 * 4) * 4, Bp + (size_t)r * 256 + c8 * 8);
    }
    CP_COMMIT();

    for (int j = 0; j < 8; j++) {
        const int buf = j & 1;
        const uint32_t* at = a_s + buf * TILEW;
        const uint32_t* bt = b_s + buf * TILEW;

        CP_WAIT0();
        __syncthreads();

        if (j < 7) {
            const uint32_t ad = a_u + ((buf ^ 1) * TILEW) * 4;
            const uint32_t bd = b_u + ((buf ^ 1) * TILEW) * 4;
            const int k0 = (j + 1) * 32;
            #pragma unroll 2
            for (int e = tid; e < 512; e += 256) {
                int r = e >> 2, c8 = e & 3;
                cp16(ad + (r * LDWH + c8 * 4) * 4, A + (size_t)(m0 + r) * 256 + k0 + c8 * 8);
            }
            #pragma unroll 2
            for (int e = tid; e < 512; e += 256) {
                int r = e >> 2, c8 = e & 3;
                cp16(bd + (r * LDWH + c8 * 4) * 4, Bp + (size_t)r * 256 + k0 + c8 * 8);
            }
            CP_COMMIT();
        }

        #pragma unroll
        for (int kt = 0; kt < 2; kt++) {
            uint32_t af[2][4];
            #pragma unroll
            for (int mt = 0; mt < 2; mt++) {
                const uint32_t* ap = at + (wm * 32 + mt * 16 + g4) * LDWH + kt * 8 + t4;
                af[mt][0] = ap[0];
                af[mt][1] = ap[8 * LDWH];
                af[mt][2] = ap[4];
                af[mt][3] = ap[8 * LDWH + 4];
            }
            const uint32_t* bp = bt + (wn * 64 + g4) * LDWH + kt * 8 + t4;
            #pragma unroll
            for (int nt = 0; nt < 8; nt++) {
                uint32_t b0 = bp[nt * 8 * LDWH];
                uint32_t b1 = bp[nt * 8 * LDWH + 4];
                mma16(acc[0][nt], af[0], b0, b1);
                mma16(acc[1][nt], af[1], b0, b1);
            }
        }
        __syncthreads();
    }

    #pragma unroll
    for (int mt = 0; mt < 2; mt++) {
        const int r0 = m0 + wm * 32 + mt * 16 + g4;
        const float bv0 = bias[r0], bv1 = bias[r0 + 8];
        #pragma unroll
        for (int nt = 0; nt < 8; nt++) {
            const int tok = n0 + wn * 64 + nt * 8 + 2 * t4;
            float v0 = acc[mt][nt][0] + bv0;
            float v1 = acc[mt][nt][1] + bv0;
            float v2 = acc[mt][nt][2] + bv1;
            float v3 = acc[mt][nt][3] + bv1;
            if (QKV_MODE) {
                if (r0 < 256) {
                    const int bh = bb * NHEAD + (r0 >> 6);
                    const int c0 = r0 & 63;
                    __half* gq = g_qh + ((size_t)bh * HWSZ + tok) * 64;
                    gq[c0]          = __float2half_rn(v0 * QSCALE);
                    gq[64 + c0]     = __float2half_rn(v1 * QSCALE);
                    gq[c0 + 8]      = __float2half_rn(v2 * QSCALE);
                    gq[64 + c0 + 8] = __float2half_rn(v3 * QSCALE);
                } else if (r0 < 512) {
                    const int bh = bb * NHEAD + ((r0 - 256) >> 6);
                    const int c0 = r0 & 63;
                    __half* gk = g_kh + ((size_t)bh * HWSZ + tok) * 64;
                    gk[c0]          = __float2half_rn(v0);
                    gk[64 + c0]     = __float2half_rn(v1);
                    gk[c0 + 8]      = __float2half_rn(v2);
                    gk[64 + c0 + 8] = __float2half_rn(v3);
                } else {
                    const int cl = r0 - 512;
                    const int bh = bb * NHEAD + (cl >> 6);
                    const int ch = cl & 63;
                    __half* gv = g_vh + ((size_t)bh * 64 + ch) * HWSZ + tok;
                    *(__half2*)gv              = __floats2half2_rn(v0, v1);
                    *(__half2*)(gv + 8 * HWSZ) = __floats2half2_rn(v2, v3);
                }
            } else {
                const float* rp = resid + ((size_t)bb * 256 + r0) * HWSZ + tok;
                float* op = out + ((size_t)bb * 256 + r0) * HWSZ + tok;
                float2 ra = *(const float2*)rp;
                float2 rb = *(const float2*)(rp + 8 * HWSZ);
                *(float2*)op              = make_float2(v0 + ra.x, v1 + ra.y);
                *(float2*)(op + 8 * HWSZ) = make_float2(v2 + rb.x, v3 + rb.y);
            }
        }
    }
}

// ============================================================
// fp16 flash attention: 4 warps x 32 rows, BN=64, ldmatrix, free-l,
// half-tile software pipelining: {S_B || ex2_A}, {PV_A || ex2_B}.
// ============================================================
#define LDW 36
#define KVW (64 * LDW)
#define ATTN_SMEM_BYTES (4 * KVW * 4)
#define ONE2 0x3C003C00u

__global__ void __launch_bounds__(128) attn_mma_kernel() {
    extern __shared__ uint32_t smw[];
    uint32_t* ks_base = smw;
    uint32_t* vs_base = smw + 2 * KVW;

    const int tid = threadIdx.x, lane = tid & 31, wid = tid >> 5;
    const int g4 = lane >> 2, t4 = lane & 3;
    const int bh = blockIdx.y;
    const int bb = bh >> 2, hh = bh & 3;
    const int i0 = blockIdx.x * 128;
    const int wrow = wid * 32;

    const __half* qg = g_qh + (size_t)bh * HWSZ * 64;
    const __half* kg = g_kh + (size_t)bh * HWSZ * 64;
    const __half* vg = g_vh + (size_t)bh * 64 * HWSZ;

    const uint32_t ks_u = smem_u32(ks_base);
    const uint32_t vs_u = smem_u32(vs_base);

    const int lm_m = lane >> 3;
    const uint32_t lm_row = (uint32_t)(((lm_m >> 1) * 8) + (lane & 7));
    const uint32_t lm_kb  = (uint32_t)((lm_m & 1) * 16);

    uint32_t qf[2][4][4];
    #pragma unroll
    for (int mt = 0; mt < 2; mt++) {
        const __half* qr0 = qg + (size_t)(i0 + wrow + mt * 16 + g4) * 64;
        const __half* qr1 = qr0 + 8 * 64;
        #pragma unroll
        for (int kt = 0; kt < 4; kt++) {
            qf[mt][kt][0] = *(const uint32_t*)(qr0 + kt * 16 + 2 * t4);
            qf[mt][kt][1] = *(const uint32_t*)(qr1 + kt * 16 + 2 * t4);
            qf[mt][kt][2] = *(const uint32_t*)(qr0 + kt * 16 + 2 * t4 + 8);
            qf[mt][kt][3] = *(const uint32_t*)(qr1 + kt * 16 + 2 * t4 + 8);
        }
    }

    float of[2][9][4];
    #pragma unroll
    for (int mt = 0; mt < 2; mt++)
        #pragma unroll
        for (int nt = 0; nt < 9; nt++)
            #pragma unroll
            for (int i = 0; i < 4; i++) of[mt][nt][i] = 0.f;

    #pragma unroll 4
    for (int e = tid; e < 512; e += 128) {
        int r = e >> 3, c = e & 7;
        cp16(ks_u + (r * LDW) * 4 + c * 16, kg + (size_t)r * 64 + c * 8);
    }
    #pragma unroll 4
    for (int e = tid; e < 512; e += 128) {
        int r = e >> 3, c = e & 7;
        cp16(vs_u + (r * LDW) * 4 + c * 16, vg + (size_t)r * HWSZ + c * 8);
    }
    CP_COMMIT();

    for (int j = 0; j < 64; j++) {
        const int buf = j & 1;
        const uint32_t klm = ks_u + (buf * KVW + lm_row * LDW) * 4 + lm_kb;
        const uint32_t vlm = vs_u + (buf * KVW + lm_row * LDW) * 4 + lm_kb;

        CP_WAIT0();
        __syncthreads();

        if (j < 63) {
            const uint32_t kd = ks_u + ((buf ^ 1) * KVW) * 4;
            const uint32_t vd = vs_u + ((buf ^ 1) * KVW) * 4;
            const __half* kn = kg + (size_t)(j + 1) * 64 * 64;
            const __half* vn = vg + (j + 1) * 64;
            #pragma unroll 4
            for (int e = tid; e < 512; e += 128) {
                int r = e >> 3, c = e & 7;
                cp16(kd + (r * LDW) * 4 + c * 16, kn + (size_t)r * 64 + c * 8);
            }
            #pragma unroll 4
            for (int e = tid; e < 512; e += 128) {
                int r = e >> 3, c = e & 7;
                cp16(vd + (r * LDW) * 4 + c * 16, vn + (size_t)r * HWSZ + c * 8);
            }
            CP_COMMIT();
        }

        float sf[2][8][4];
        #pragma unroll
        for (int mt = 0; mt < 2; mt++)
            #pragma unroll
            for (int nt = 0; nt < 8; nt++)
                #pragma unroll
                for (int i = 0; i < 4; i++) sf[mt][nt][i] = 0.f;

        // ---- S_A: keys 0..31 (ntp 0,1) ----
        #pragma unroll
        for (int kt = 0; kt < 4; kt++) {
            #pragma unroll
            for (int ntp = 0; ntp < 2; ntp++) {
                uint32_t br[4];
                ldsm4(br, klm + (ntp * 16 * LDW) * 4 + kt * 32);
                mma16(sf[0][2 * ntp],     qf[0][kt], br[0], br[1]);
                mma16(sf[1][2 * ntp],     qf[1][kt], br[0], br[1]);
                mma16(sf[0][2 * ntp + 1], qf[0][kt], br[2], br[3]);
                mma16(sf[1][2 * ntp + 1], qf[1][kt], br[2], br[3]);
            }
        }

        uint32_t pa[2][4][4];

        // ---- S_B (keys 32..63, ntp 2,3)  ||  ex2_A (sf nt 0..3 -> pa kt 0,1) ----
        #pragma unroll
        for (int kt = 0; kt < 4; kt++) {
            #pragma unroll
            for (int ntp = 2; ntp < 4; ntp++) {
                uint32_t br[4];
                ldsm4(br, klm + (ntp * 16 * LDW) * 4 + kt * 32);
                mma16(sf[0][2 * ntp],     qf[0][kt], br[0], br[1]);
                mma16(sf[1][2 * ntp],     qf[1][kt], br[0], br[1]);
                mma16(sf[0][2 * ntp + 1], qf[0][kt], br[2], br[3]);
                mma16(sf[1][2 * ntp + 1], qf[1][kt], br[2], br[3]);
            }
        }
        #pragma unroll
        for (int mt = 0; mt < 2; mt++)
            #pragma unroll
            for (int nt = 0; nt < 4; nt++) {
                float p0 = ex2f(sf[mt][nt][0]);
                float p1 = ex2f(sf[mt][nt][1]);
                float p2 = ex2f(sf[mt][nt][2]);
                float p3 = ex2f(sf[mt][nt][3]);
                pa[mt][nt >> 1][(nt & 1) * 2]     = pack_h2(p0, p1);
                pa[mt][nt >> 1][(nt & 1) * 2 + 1] = pack_h2(p2, p3);
            }

        // ---- PV_A (pa kt 0,1)  ||  ex2_B (sf nt 4..7 -> pa kt 2,3) ----
        #pragma unroll
        for (int kt = 0; kt < 2; kt++) {
            #pragma unroll
            for (int ntp = 0; ntp < 4; ntp++) {
                uint32_t br[4];
                ldsm4(br, vlm + (ntp * 16 * LDW) * 4 + kt * 32);
                mma16(of[0][2 * ntp],     pa[0][kt], br[0], br[1]);
                mma16(of[1][2 * ntp],     pa[1][kt], br[0], br[1]);
                mma16(of[0][2 * ntp + 1], pa[0][kt], br[2], br[3]);
                mma16(of[1][2 * ntp + 1], pa[1][kt], br[2], br[3]);
            }
            mma16(of[0][8], pa[0][kt], ONE2, ONE2);
            mma16(of[1][8], pa[1][kt], ONE2, ONE2);
        }
        #pragma unroll
        for (int mt = 0; mt < 2; mt++)
            #pragma unroll
            for (int nt = 4; nt < 8; nt++) {
                float p0 = ex2f(sf[mt][nt][0]);
                float p1 = ex2f(sf[mt][nt][1]);
                float p2 = ex2f(sf[mt][nt][2]);
                float p3 = ex2f(sf[mt][nt][3]);
                pa[mt][nt >> 1][(nt & 1) * 2]     = pack_h2(p0, p1);
                pa[mt][nt >> 1][(nt & 1) * 2 + 1] = pack_h2(p2, p3);
            }

        // ---- PV_B (pa kt 2,3) ----
        #pragma unroll
        for (int kt = 2; kt < 4; kt++) {
            #pragma unroll
            for (int ntp = 0; ntp < 4; ntp++) {
                uint32_t br[4];
                ldsm4(br, vlm + (ntp * 16 * LDW) * 4 + kt * 32);
                mma16(of[0][2 * ntp],     pa[0][kt], br[0], br[1]);
                mma16(of[1][2 * ntp],     pa[1][kt], br[0], br[1]);
                mma16(of[0][2 * ntp + 1], pa[0][kt], br[2], br[3]);
                mma16(of[1][2 * ntp + 1], pa[1][kt], br[2], br[3]);
            }
            mma16(of[0][8], pa[0][kt], ONE2, ONE2);
            mma16(of[1][8], pa[1][kt], ONE2, ONE2);
        }
    }

    #pragma unroll
    for (int mt = 0; mt < 2; mt++) {
        float inv0 = 1.f / of[mt][8][0];
        float inv1 = 1.f / of[mt][8][2];
        int tok = i0 + wrow + mt * 16 + g4;
        __half* d0 = g_oh + ((size_t)bb * HWSZ + tok) * 256 + hh * 64;
        __half* d1 = d0 + 8 * 256;
        #pragma unroll
        for (int nt = 0; nt < 8; nt++) {
            int ch = nt * 8 + 2 * t4;
            *(__half2*)(d0 + ch) = __floats2half2_rn(of[mt][nt][0] * inv0,
                                                     of[mt][nt][1] * inv0);
            *(__half2*)(d1 + ch) = __floats2half2_rn(of[mt][nt][2] * inv1,
                                                     of[mt][nt][3] * inv1);
        }
    }
}

// ============================================================
extern "C" void kernel_launch(void* const* d_in, const int* in_sizes, int n_in,
                              void* d_out, int out_size) {
    const float* x      = (const float*)d_in[0];
    const float* norm_w = (const float*)d_in[1];
    const float* norm_b = (const float*)d_in[2];
    const float* qkv_w  = (const float*)d_in[3];
    const float* qkv_b  = (const float*)d_in[4];
    const float* proj_w = (const float*)d_in[5];
    const float* proj_b = (const float*)d_in[6];
    float* out = (float*)d_out;

    void *pht, *poh, *pwq, *pwp;
    cudaGetSymbolAddress(&pht, g_ht);
    cudaGetSymbolAddress(&poh, g_oh);
    cudaGetSymbolAddress(&pwq, g_wqkv);
    cudaGetSymbolAddress(&pwp, g_wproj);

    cudaFuncSetAttribute(gemm_h_kernel<768, true>,
                         cudaFuncAttributeMaxDynamicSharedMemorySize, GEMM_SMEM_BYTES);
    cudaFuncSetAttribute(gemm_h_kernel<256, false>,
                         cudaFuncAttributeMaxDynamicSharedMemorySize, GEMM_SMEM_BYTES);
    cudaFuncSetAttribute(attn_mma_kernel,
                         cudaFuncAttributeMaxDynamicSharedMemorySize, ATTN_SMEM_BYTES);

    convert_w_kernel<<<320, 256>>>(qkv_w, proj_w);
    gn_partial_kernel<<<1024, 128>>>(x);
    gn_final_kernel<<<1, 32>>>();
    gn_norm_kernel<<<dim3(HWSZ / 128, 32), 256>>>(x, norm_w, norm_b);

    gemm_h_kernel<768, true><<<dim3(HWSZ / 128, 768 / 128, BATCH), 256, GEMM_SMEM_BYTES>>>(
        (const __half*)pwq, (const __half*)pht, qkv_b, nullptr, nullptr);

    attn_mma_kernel<<<dim3(HWSZ / 128, NBH), 128, ATTN_SMEM_BYTES>>>();

    gemm_h_kernel<256, false><<<dim3(HWSZ / 128, 256 / 128, BATCH), 256, GEMM_SMEM_BYTES>>>(
        (const __half*)pwp, (const __half*)poh, proj_b, x, out);
}

// round 11
// speedup vs baseline: 1.1385x; 1.0069x over previous
#include <cuda_runtime.h>
#include <cuda_fp16.h>
#include <math.h>
#include <stdint.h>

#define CC 256
#define HWSZ 4096
#define BATCH 4
#define NHEAD 4
#define NBH 16

// -------- scratch (device globals; no allocations allowed) --------
__device__ __half g_ht [(size_t)BATCH * HWSZ * CC];      // normalized input, [b][tok][c] half
__device__ __half g_oh [(size_t)BATCH * HWSZ * CC];      // attention out, [b][tok][c] half
__device__ __half g_qh [(size_t)NBH * HWSZ * 64];        // q: [bh][tok][c] half, *0.125*log2e
__device__ __half g_kh [(size_t)NBH * HWSZ * 64];        // k: [bh][tok][c] half
__device__ __half g_vh [(size_t)NBH * 64 * HWSZ];        // v: [bh][c][tok] half
__device__ __half g_wqkv[768 * 256];                     // fp16 weights
__device__ __half g_wproj[256 * 256];
__device__ float2 g_part[1024];                          // per-slice (sum, sumsq)
__device__ float2 g_stats[32];                           // per (b,group) (mean, rstd)

// ============================================================
// helpers (sm_80-baseline PTX only)
// ============================================================
__device__ __forceinline__ uint32_t smem_u32(const void* p) {
    uint32_t a;
    asm("{ .reg .u64 t; cvta.to.shared.u64 t, %1; cvt.u32.u64 %0, t; }" : "=r"(a) : "l"(p));
    return a;
}
__device__ __forceinline__ float ex2f(float x) {
    float r;
    asm("ex2.approx.ftz.f32 %0, %1;" : "=f"(r) : "f"(x));
    return r;
}
__device__ __forceinline__ uint32_t pack_h2(float lo, float hi) {
    uint32_t d;
    asm("cvt.rn.f16x2.f32 %0, %1, %2;" : "=r"(d) : "f"(hi), "f"(lo));
    return d;
}
__device__ __forceinline__ void cp16(uint32_t dst, const void* src) {
    asm volatile("cp.async.cg.shared.global [%0], [%1], 16;" :: "r"(dst), "l"(src) : "memory");
}
#define CP_COMMIT()  asm volatile("cp.async.commit_group;" ::: "memory")
#define CP_WAIT0()   asm volatile("cp.async.wait_group 0;" ::: "memory")

__device__ __forceinline__ void ldsm4(uint32_t r[4], uint32_t addr) {
    asm volatile("ldmatrix.sync.aligned.m8n8.x4.shared.b16 {%0,%1,%2,%3}, [%4];"
        : "=r"(r[0]), "=r"(r[1]), "=r"(r[2]), "=r"(r[3]) : "r"(addr));
}

// fp16 m16n8k16, fp32 accum
__device__ __forceinline__ void mma16(float c[4], const uint32_t a_[4], uint32_t b0, uint32_t b1) {
    asm volatile("mma.sync.aligned.m16n8k16.row.col.f32.f16.f16.f32 "
        "{%0,%1,%2,%3}, {%4,%5,%6,%7}, {%8,%9}, {%0,%1,%2,%3};"
        : "+f"(c[0]), "+f"(c[1]), "+f"(c[2]), "+f"(c[3])
        : "r"(a_[0]), "r"(a_[1]), "r"(a_[2]), "r"(a_[3]),
          "r"(b0), "r"(b1));
}

// ============================================================
// Weight conversion fp32 -> fp16 (vectorized; once per launch)
// ============================================================
__global__ void convert_w_kernel(const float* __restrict__ qkv_w,
                                 const float* __restrict__ proj_w) {
    int i = (blockIdx.x * 256 + threadIdx.x) * 4;
    float4 v;
    __half2 h0, h1;
    if (i < 768 * 256) {
        v = *(const float4*)(qkv_w + i);
        h0 = __floats2half2_rn(v.x, v.y);
        h1 = __floats2half2_rn(v.z, v.w);
        *(__half2*)(g_wqkv + i)     = h0;
        *(__half2*)(g_wqkv + i + 2) = h1;
    } else {
        int k = i - 768 * 256;
        v = *(const float4*)(proj_w + k);
        h0 = __floats2half2_rn(v.x, v.y);
        h1 = __floats2half2_rn(v.z, v.w);
        *(__half2*)(g_wproj + k)     = h0;
        *(__half2*)(g_wproj + k + 2) = h1;
    }
}

// ============================================================
// GroupNorm, 3 phases (unchanged)
// ============================================================
__global__ void gn_partial_kernel(const float* __restrict__ x) {
    const float* xp = x + (size_t)blockIdx.x * 4096;
    int tid = threadIdx.x;
    float s = 0.f, ss = 0.f;
    #pragma unroll 8
    for (int i = tid * 4; i < 4096; i += 512) {
        float4 v = *(const float4*)(xp + i);
        s  += v.x + v.y + v.z + v.w;
        ss += v.x * v.x + v.y * v.y + v.z * v.z + v.w * v.w;
    }
    __shared__ float rs[128], rss[128];
    rs[tid] = s; rss[tid] = ss;
    __syncthreads();
    for (int o = 64; o > 0; o >>= 1) {
        if (tid < o) { rs[tid] += rs[tid + o]; rss[tid] += rss[tid + o]; }
        __syncthreads();
    }
    if (tid == 0) g_part[blockIdx.x] = make_float2(rs[0], rss[0]);
}

__global__ void gn_final_kernel() {
    int t = threadIdx.x;
    float s = 0.f, ss = 0.f;
    #pragma unroll
    for (int i = 0; i < 32; i++) { float2 p = g_part[t * 32 + i]; s += p.x; ss += p.y; }
    float mean = s / 131072.f;
    float var  = ss / 131072.f - mean * mean;
    g_stats[t] = make_float2(mean, rsqrtf(var + 1e-5f));
}

__global__ void gn_norm_kernel(const float* __restrict__ x,
                               const float* __restrict__ w,
                               const float* __restrict__ b) {
    __shared__ float tile[32][129];
    const int t0 = blockIdx.x * 128;
    const int bg = blockIdx.y;
    const int bb = bg >> 3, gg = bg & 7;
    const int tid = threadIdx.x;

    const float* xp = x + ((size_t)bb * 256 + gg * 32) * HWSZ + t0;
    #pragma unroll 4
    for (int i = tid; i < 1024; i += 256) {
        int row = i >> 5, c4 = i & 31;
        float4 v = *(const float4*)(xp + (size_t)row * HWSZ + c4 * 4);
        tile[row][c4 * 4 + 0] = v.x;
        tile[row][c4 * 4 + 1] = v.y;
        tile[row][c4 * 4 + 2] = v.z;
        tile[row][c4 * 4 + 3] = v.w;
    }
    float2 st = g_stats[bg];
    __syncthreads();

    const int tok = tid >> 1, seg = tid & 1;
    __half hv[16];
    #pragma unroll
    for (int i = 0; i < 16; i++) {
        int cc = seg * 16 + i;
        int c = gg * 32 + cc;
        float sc = st.y * w[c];
        float of = b[c] - st.x * sc;
        hv[i] = __float2half_rn(tile[cc][tok] * sc + of);
    }
    __half* dst = g_ht + ((size_t)bb * HWSZ + t0 + tok) * 256 + gg * 32 + seg * 16;
    *(uint4*)dst       = *(uint4*)hv;
    *(uint4*)(dst + 8) = *(uint4*)(hv + 8);
}

// ============================================================
// fp16 tensor-core GEMM. QKV mode: smem-staged epilogue with
// coalesced uint4 stores (replaces 2-byte scatter stores).
// ============================================================
#define LDWH 20
#define TILEW (128 * LDWH)
#define GEMM_SMEM_BYTES (4 * TILEW * 4)
#define QSCALE 0.18033688011112042f
#define EPL 136                          // halves per staged row (pad 8)

template<int M_TOTAL, bool QKV_MODE>
__global__ void __launch_bounds__(256, 2) gemm_h_kernel(
        const __half* __restrict__ A,
        const __half* __restrict__ Bt,
        const float* __restrict__ bias,
        const float* __restrict__ resid,
        float* __restrict__ out) {
    extern __shared__ uint32_t sw[];
    uint32_t* a_s = sw;
    uint32_t* b_s = sw + 2 * TILEW;
    const uint32_t a_u = smem_u32(a_s);
    const uint32_t b_u = smem_u32(b_s);

    const int tid = threadIdx.x, lane = tid & 31, wid = tid >> 5;
    const int g4 = lane >> 2, t4 = lane & 3;
    const int wm = wid >> 1, wn = wid & 1;
    const int bb = blockIdx.z;
    const int m0 = blockIdx.y * 128;
    const int n0 = blockIdx.x * 128;
    const __half* Bp = Bt + (size_t)bb * HWSZ * 256 + (size_t)n0 * 256;

    float acc[2][8][4];
    #pragma unroll
    for (int mt = 0; mt < 2; mt++)
        #pragma unroll
        for (int nt = 0; nt < 8; nt++)
            #pragma unroll
            for (int i = 0; i < 4; i++) acc[mt][nt][i] = 0.f;

    #pragma unroll 2
    for (int e = tid; e < 512; e += 256) {
        int r = e >> 2, c8 = e & 3;
        cp16(a_u + (r * LDWH + c8 * 4) * 4, A + (size_t)(m0 + r) * 256 + c8 * 8);
    }
    #pragma unroll 2
    for (int e = tid; e < 512; e += 256) {
        int r = e >> 2, c8 = e & 3;
        cp16(b_u + (r * LDWH + c8 * 4) * 4, Bp + (size_t)r * 256 + c8 * 8);
    }
    CP_COMMIT();

    for (int j = 0; j < 8; j++) {
        const int buf = j & 1;
        const uint32_t* at = a_s + buf * TILEW;
        const uint32_t* bt = b_s + buf * TILEW;

        CP_WAIT0();
        __syncthreads();

        if (j < 7) {
            const uint32_t ad = a_u + ((buf ^ 1) * TILEW) * 4;
            const uint32_t bd = b_u + ((buf ^ 1) * TILEW) * 4;
            const int k0 = (j + 1) * 32;
            #pragma unroll 2
            for (int e = tid; e < 512; e += 256) {
                int r = e >> 2, c8 = e & 3;
                cp16(ad + (r * LDWH + c8 * 4) * 4, A + (size_t)(m0 + r) * 256 + k0 + c8 * 8);
            }
            #pragma unroll 2
            for (int e = tid; e < 512; e += 256) {
                int r = e >> 2, c8 = e & 3;
                cp16(bd + (r * LDWH + c8 * 4) * 4, Bp + (size_t)r * 256 + k0 + c8 * 8);
            }
            CP_COMMIT();
        }

        #pragma unroll
        for (int kt = 0; kt < 2; kt++) {
            uint32_t af[2][4];
            #pragma unroll
            for (int mt = 0; mt < 2; mt++) {
                const uint32_t* ap = at + (wm * 32 + mt * 16 + g4) * LDWH + kt * 8 + t4;
                af[mt][0] = ap[0];
                af[mt][1] = ap[8 * LDWH];
                af[mt][2] = ap[4];
                af[mt][3] = ap[8 * LDWH + 4];
            }
            const uint32_t* bp = bt + (wn * 64 + g4) * LDWH + kt * 8 + t4;
            #pragma unroll
            for (int nt = 0; nt < 8; nt++) {
                uint32_t b0 = bp[nt * 8 * LDWH];
                uint32_t b1 = bp[nt * 8 * LDWH + 4];
                mma16(acc[0][nt], af[0], b0, b1);
                mma16(acc[1][nt], af[1], b0, b1);
            }
        }
        __syncthreads();
    }

    // ---- epilogue ----
    if (QKV_MODE) {
        // stage tile in smem as halves, then coalesced uint4 stores
        uint16_t* ep = (uint16_t*)sw;
        const bool is_v = (m0 >= 512);
        const float sc = (m0 < 256) ? QSCALE : 1.0f;

        #pragma unroll
        for (int mt = 0; mt < 2; mt++) {
            const int r = wm * 32 + mt * 16 + g4;            // local row
            const float bv0 = bias[m0 + r], bv1 = bias[m0 + r + 8];
            #pragma unroll
            for (int nt = 0; nt < 8; nt++) {
                const int tl = wn * 64 + nt * 8 + 2 * t4;    // local token (even)
                __half h0 = __float2half_rn((acc[mt][nt][0] + bv0) * sc);
                __half h1 = __float2half_rn((acc[mt][nt][1] + bv0) * sc);
                __half h2 = __float2half_rn((acc[mt][nt][2] + bv1) * sc);
                __half h3 = __float2half_rn((acc[mt][nt][3] + bv1) * sc);
                if (is_v) {
                    // stage [row][tok]: adjacent toks contiguous -> half2 STS
                    __half2 p01; p01.x = h0; p01.y = h1;
                    __half2 p23; p23.x = h2; p23.y = h3;
                    *(__half2*)&ep[(r)     * EPL + tl] = p01;
                    *(__half2*)&ep[(r + 8) * EPL + tl] = p23;
                } else {
                    // stage [tok][row]: scalar STS (half-pairs merge per word)
                    ep[(tl)     * EPL + r]     = __half_as_ushort(h0);
                    ep[(tl + 1) * EPL + r]     = __half_as_ushort(h1);
                    ep[(tl)     * EPL + r + 8] = __half_as_ushort(h2);
                    ep[(tl + 1) * EPL + r + 8] = __half_as_ushort(h3);
                }
            }
        }
        __syncthreads();

        // copy out: 2048 uint4 chunks, 8 per thread, coalesced
        #pragma unroll
        for (int e = tid; e < 2048; e += 256) {
            const int a = e >> 4, c8 = e & 15;    // a = tok (q/k) or row (v)
            uint4 val = *(uint4*)&ep[a * EPL + c8 * 8];
            if (is_v) {
                const int ch = m0 - 512 + a;      // 0..255
                __half* gv = g_vh + ((size_t)(bb * 4 + (ch >> 6)) * 64 + (ch & 63)) * HWSZ
                           + n0 + c8 * 8;
                *(uint4*)gv = val;
            } else {
                const int gm = m0 + c8 * 8;       // global row of chunk
                const int tok = n0 + a;
                if (gm < 256) {
                    __half* gq = g_qh + ((size_t)(bb * 4 + (gm >> 6)) * HWSZ + tok) * 64
                               + (gm & 63);
                    *(uint4*)gq = val;
                } else {
                    __half* gk = g_kh + ((size_t)(bb * 4 + ((gm - 256) >> 6)) * HWSZ + tok) * 64
                               + (gm & 63);
                    *(uint4*)gk = val;
                }
            }
        }
    } else {
        #pragma unroll
        for (int mt = 0; mt < 2; mt++) {
            const int r0 = m0 + wm * 32 + mt * 16 + g4;
            const float bv0 = bias[r0], bv1 = bias[r0 + 8];
            #pragma unroll
            for (int nt = 0; nt < 8; nt++) {
                const int tok = n0 + wn * 64 + nt * 8 + 2 * t4;
                float v0 = acc[mt][nt][0] + bv0;
                float v1 = acc[mt][nt][1] + bv0;
                float v2 = acc[mt][nt][2] + bv1;
                float v3 = acc[mt][nt][3] + bv1;
                const float* rp = resid + ((size_t)bb * 256 + r0) * HWSZ + tok;
                float* op = out + ((size_t)bb * 256 + r0) * HWSZ + tok;
                float2 ra = *(const float2*)rp;
                float2 rb = *(const float2*)(rp + 8 * HWSZ);
                *(float2*)op              = make_float2(v0 + ra.x, v1 + ra.y);
                *(float2*)(op + 8 * HWSZ) = make_float2(v2 + rb.x, v3 + rb.y);
            }
        }
    }
}

// ============================================================
// fp16 flash attention (unchanged from R10 best config).
// ============================================================
#define LDW 36
#define KVW (64 * LDW)
#define ATTN_SMEM_BYTES (4 * KVW * 4)
#define ONE2 0x3C003C00u

__global__ void __launch_bounds__(128) attn_mma_kernel() {
    extern __shared__ uint32_t smw[];
    uint32_t* ks_base = smw;
    uint32_t* vs_base = smw + 2 * KVW;

    const int tid = threadIdx.x, lane = tid & 31, wid = tid >> 5;
    const int g4 = lane >> 2, t4 = lane & 3;
    const int bh = blockIdx.y;
    const int bb = bh >> 2, hh = bh & 3;
    const int i0 = blockIdx.x * 128;
    const int wrow = wid * 32;

    const __half* qg = g_qh + (size_t)bh * HWSZ * 64;
    const __half* kg = g_kh + (size_t)bh * HWSZ * 64;
    const __half* vg = g_vh + (size_t)bh * 64 * HWSZ;

    const uint32_t ks_u = smem_u32(ks_base);
    const uint32_t vs_u = smem_u32(vs_base);

    const int lm_m = lane >> 3;
    const uint32_t lm_row = (uint32_t)(((lm_m >> 1) * 8) + (lane & 7));
    const uint32_t lm_kb  = (uint32_t)((lm_m & 1) * 16);

    uint32_t qf[2][4][4];
    #pragma unroll
    for (int mt = 0; mt < 2; mt++) {
        const __half* qr0 = qg + (size_t)(i0 + wrow + mt * 16 + g4) * 64;
        const __half* qr1 = qr0 + 8 * 64;
        #pragma unroll
        for (int kt = 0; kt < 4; kt++) {
            qf[mt][kt][0] = *(const uint32_t*)(qr0 + kt * 16 + 2 * t4);
            qf[mt][kt][1] = *(const uint32_t*)(qr1 + kt * 16 + 2 * t4);
            qf[mt][kt][2] = *(const uint32_t*)(qr0 + kt * 16 + 2 * t4 + 8);
            qf[mt][kt][3] = *(const uint32_t*)(qr1 + kt * 16 + 2 * t4 + 8);
        }
    }

    float of[2][9][4];
    #pragma unroll
    for (int mt = 0; mt < 2; mt++)
        #pragma unroll
        for (int nt = 0; nt < 9; nt++)
            #pragma unroll
            for (int i = 0; i < 4; i++) of[mt][nt][i] = 0.f;

    #pragma unroll 4
    for (int e = tid; e < 512; e += 128) {
        int r = e >> 3, c = e & 7;
        cp16(ks_u + (r * LDW) * 4 + c * 16, kg + (size_t)r * 64 + c * 8);
    }
    #pragma unroll 4
    for (int e = tid; e < 512; e += 128) {
        int r = e >> 3, c = e & 7;
        cp16(vs_u + (r * LDW) * 4 + c * 16, vg + (size_t)r * HWSZ + c * 8);
    }
    CP_COMMIT();

    for (int j = 0; j < 64; j++) {
        const int buf = j & 1;
        const uint32_t klm = ks_u + (buf * KVW + lm_row * LDW) * 4 + lm_kb;
        const uint32_t vlm = vs_u + (buf * KVW + lm_row * LDW) * 4 + lm_kb;

        CP_WAIT0();
        __syncthreads();

        if (j < 63) {
            const uint32_t kd = ks_u + ((buf ^ 1) * KVW) * 4;
            const uint32_t vd = vs_u + ((buf ^ 1) * KVW) * 4;
            const __half* kn = kg + (size_t)(j + 1) * 64 * 64;
            const __half* vn = vg + (j + 1) * 64;
            #pragma unroll 4
            for (int e = tid; e < 512; e += 128) {
                int r = e >> 3, c = e & 7;
                cp16(kd + (r * LDW) * 4 + c * 16, kn + (size_t)r * 64 + c * 8);
            }
            #pragma unroll 4
            for (int e = tid; e < 512; e += 128) {
                int r = e >> 3, c = e & 7;
                cp16(vd + (r * LDW) * 4 + c * 16, vn + (size_t)r * HWSZ + c * 8);
            }
            CP_COMMIT();
        }

        float sf[2][8][4];
        #pragma unroll
        for (int mt = 0; mt < 2; mt++)
            #pragma unroll
            for (int nt = 0; nt < 8; nt++)
                #pragma unroll
                for (int i = 0; i < 4; i++) sf[mt][nt][i] = 0.f;

        #pragma unroll
        for (int kt = 0; kt < 4; kt++) {
            #pragma unroll
            for (int ntp = 0; ntp < 2; ntp++) {
                uint32_t br[4];
                ldsm4(br, klm + (ntp * 16 * LDW) * 4 + kt * 32);
                mma16(sf[0][2 * ntp],     qf[0][kt], br[0], br[1]);
                mma16(sf[1][2 * ntp],     qf[1][kt], br[0], br[1]);
                mma16(sf[0][2 * ntp + 1], qf[0][kt], br[2], br[3]);
                mma16(sf[1][2 * ntp + 1], qf[1][kt], br[2], br[3]);
            }
        }

        uint32_t pa[2][4][4];

        #pragma unroll
        for (int kt = 0; kt < 4; kt++) {
            #pragma unroll
            for (int ntp = 2; ntp < 4; ntp++) {
                uint32_t br[4];
                ldsm4(br, klm + (ntp * 16 * LDW) * 4 + kt * 32);
                mma16(sf[0][2 * ntp],     qf[0][kt], br[0], br[1]);
                mma16(sf[1][2 * ntp],     qf[1][kt], br[0], br[1]);
                mma16(sf[0][2 * ntp + 1], qf[0][kt], br[2], br[3]);
                mma16(sf[1][2 * ntp + 1], qf[1][kt], br[2], br[3]);
            }
        }
        #pragma unroll
        for (int mt = 0; mt < 2; mt++)
            #pragma unroll
            for (int nt = 0; nt < 4; nt++) {
                float p0 = ex2f(sf[mt][nt][0]);
                float p1 = ex2f(sf[mt][nt][1]);
                float p2 = ex2f(sf[mt][nt][2]);
                float p3 = ex2f(sf[mt][nt][3]);
                pa[mt][nt >> 1][(nt & 1) * 2]     = pack_h2(p0, p1);
                pa[mt][nt >> 1][(nt & 1) * 2 + 1] = pack_h2(p2, p3);
            }

        #pragma unroll
        for (int kt = 0; kt < 2; kt++) {
            #pragma unroll
            for (int ntp = 0; ntp < 4; ntp++) {
                uint32_t br[4];
                ldsm4(br, vlm + (ntp * 16 * LDW) * 4 + kt * 32);
                mma16(of[0][2 * ntp],     pa[0][kt], br[0], br[1]);
                mma16(of[1][2 * ntp],     pa[1][kt], br[0], br[1]);
                mma16(of[0][2 * ntp + 1], pa[0][kt], br[2], br[3]);
                mma16(of[1][2 * ntp + 1], pa[1][kt], br[2], br[3]);
            }
            mma16(of[0][8], pa[0][kt], ONE2, ONE2);
            mma16(of[1][8], pa[1][kt], ONE2, ONE2);
        }
        #pragma unroll
        for (int mt = 0; mt < 2; mt++)
            #pragma unroll
            for (int nt = 4; nt < 8; nt++) {
                float p0 = ex2f(sf[mt][nt][0]);
                float p1 = ex2f(sf[mt][nt][1]);
                float p2 = ex2f(sf[mt][nt][2]);
                float p3 = ex2f(sf[mt][nt][3]);
                pa[mt][nt >> 1][(nt & 1) * 2]     = pack_h2(p0, p1);
                pa[mt][nt >> 1][(nt & 1) * 2 + 1] = pack_h2(p2, p3);
            }

        #pragma unroll
        for (int kt = 2; kt < 4; kt++) {
            #pragma unroll
            for (int ntp = 0; ntp < 4; ntp++) {
                uint32_t br[4];
                ldsm4(br, vlm + (ntp * 16 * LDW) * 4 + kt * 32);
                mma16(of[0][2 * ntp],     pa[0][kt], br[0], br[1]);
                mma16(of[1][2 * ntp],     pa[1][kt], br[0], br[1]);
                mma16(of[0][2 * ntp + 1], pa[0][kt], br[2], br[3]);
                mma16(of[1][2 * ntp + 1], pa[1][kt], br[2], br[3]);
            }
            mma16(of[0][8], pa[0][kt], ONE2, ONE2);
            mma16(of[1][8], pa[1][kt], ONE2, ONE2);
        }
    }

    #pragma unroll
    for (int mt = 0; mt < 2; mt++) {
        float inv0 = 1.f / of[mt][8][0];
        float inv1 = 1.f / of[mt][8][2];
        int tok = i0 + wrow + mt * 16 + g4;
        __half* d0 = g_oh + ((size_t)bb * HWSZ + tok) * 256 + hh * 64;
        __half* d1 = d0 + 8 * 256;
        #pragma unroll
        for (int nt = 0; nt < 8; nt++) {
            int ch = nt * 8 + 2 * t4;
            *(__half2*)(d0 + ch) = __floats2half2_rn(of[mt][nt][0] * inv0,
                                                     of[mt][nt][1] * inv0);
            *(__half2*)(d1 + ch) = __floats2half2_rn(of[mt][nt][2] * inv1,
                                                     of[mt][nt][3] * inv1);
        }
    }
}

// ============================================================
extern "C" void kernel_launch(void* const* d_in, const int* in_sizes, int n_in,
                              void* d_out, int out_size) {
    const float* x      = (const float*)d_in[0];
    const float* norm_w = (const float*)d_in[1];
    const float* norm_b = (const float*)d_in[2];
    const float* qkv_w  = (const float*)d_in[3];
    const float* qkv_b  = (const float*)d_in[4];
    const float* proj_w = (const float*)d_in[5];
    const float* proj_b = (const float*)d_in[6];
    float* out = (float*)d_out;

    void *pht, *poh, *pwq, *pwp;
    cudaGetSymbolAddress(&pht, g_ht);
    cudaGetSymbolAddress(&poh, g_oh);
    cudaGetSymbolAddress(&pwq, g_wqkv);
    cudaGetSymbolAddress(&pwp, g_wproj);

    cudaFuncSetAttribute(gemm_h_kernel<768, true>,
                         cudaFuncAttributeMaxDynamicSharedMemorySize, GEMM_SMEM_BYTES);
    cudaFuncSetAttribute(gemm_h_kernel<256, false>,
                         cudaFuncAttributeMaxDynamicSharedMemorySize, GEMM_SMEM_BYTES);
    cudaFuncSetAttribute(attn_mma_kernel,
                         cudaFuncAttributeMaxDynamicSharedMemorySize, ATTN_SMEM_BYTES);

    convert_w_kernel<<<320, 256>>>(qkv_w, proj_w);
    gn_partial_kernel<<<1024, 128>>>(x);
    gn_final_kernel<<<1, 32>>>();
    gn_norm_kernel<<<dim3(HWSZ / 128, 32), 256>>>(x, norm_w, norm_b);

    gemm_h_kernel<768, true><<<dim3(HWSZ / 128, 768 / 128, BATCH), 256, GEMM_SMEM_BYTES>>>(
        (const __half*)pwq, (const __half*)pht, qkv_b, nullptr, nullptr);

    attn_mma_kernel<<<dim3(HWSZ / 128, NBH), 128, ATTN_SMEM_BYTES>>>();

    gemm_h_kernel<256, false><<<dim3(HWSZ / 128, 256 / 128, BATCH), 256, GEMM_SMEM_BYTES>>>(
        (const __half*)pwp, (const __half*)poh, proj_b, x, out);
}

// round 12
// speedup vs baseline: 1.1666x; 1.0247x over previous
#include <cuda_runtime.h>
#include <cuda_fp16.h>
#include <math.h>
#include <stdint.h>

#define CC 256
#define HWSZ 4096
#define BATCH 4
#define NHEAD 4
#define NBH 16

// -------- scratch (device globals; no allocations allowed) --------
__device__ __half g_ht [(size_t)BATCH * HWSZ * CC];      // normalized input, [b][tok][c] half
__device__ __half g_oh [(size_t)BATCH * HWSZ * CC];      // attention out, [b][tok][c] half
__device__ __half g_qh [(size_t)NBH * HWSZ * 64];        // q: [bh][tok][c] half, *0.125*log2e
__device__ __half g_kh [(size_t)NBH * HWSZ * 64];        // k: [bh][tok][c] half
__device__ __half g_vh [(size_t)NBH * 64 * HWSZ];        // v: [bh][c][tok] half
__device__ __half g_wqkv[768 * 256];                     // fp16 weights
__device__ __half g_wproj[256 * 256];
__device__ float2 g_part[1024];                          // per-slice (sum, sumsq)
__device__ float2 g_stats[32];                           // per (b,group) (mean, rstd)

// ============================================================
// helpers (sm_80-baseline PTX only)
// ============================================================
__device__ __forceinline__ uint32_t smem_u32(const void* p) {
    uint32_t a;
    asm("{ .reg .u64 t; cvta.to.shared.u64 t, %1; cvt.u32.u64 %0, t; }" : "=r"(a) : "l"(p));
    return a;
}
__device__ __forceinline__ float ex2f(float x) {
    float r;
    asm("ex2.approx.ftz.f32 %0, %1;" : "=f"(r) : "f"(x));
    return r;
}
__device__ __forceinline__ uint32_t pack_h2(float lo, float hi) {
    uint32_t d;
    asm("cvt.rn.f16x2.f32 %0, %1, %2;" : "=r"(d) : "f"(hi), "f"(lo));
    return d;
}
__device__ __forceinline__ void cp16(uint32_t dst, const void* src) {
    asm volatile("cp.async.cg.shared.global [%0], [%1], 16;" :: "r"(dst), "l"(src) : "memory");
}
#define CP_COMMIT()  asm volatile("cp.async.commit_group;" ::: "memory")
#define CP_WAIT0()   asm volatile("cp.async.wait_group 0;" ::: "memory")

__device__ __forceinline__ void ldsm4(uint32_t r[4], uint32_t addr) {
    asm volatile("ldmatrix.sync.aligned.m8n8.x4.shared.b16 {%0,%1,%2,%3}, [%4];"
        : "=r"(r[0]), "=r"(r[1]), "=r"(r[2]), "=r"(r[3]) : "r"(addr));
}

// fp16 m16n8k16, fp32 accum
__device__ __forceinline__ void mma16(float c[4], const uint32_t a_[4], uint32_t b0, uint32_t b1) {
    asm volatile("mma.sync.aligned.m16n8k16.row.col.f32.f16.f16.f32 "
        "{%0,%1,%2,%3}, {%4,%5,%6,%7}, {%8,%9}, {%0,%1,%2,%3};"
        : "+f"(c[0]), "+f"(c[1]), "+f"(c[2]), "+f"(c[3])
        : "r"(a_[0]), "r"(a_[1]), "r"(a_[2]), "r"(a_[3]),
          "r"(b0), "r"(b1));
}

// ============================================================
// Weight conversion fp32 -> fp16 (vectorized; once per launch)
// ============================================================
__global__ void convert_w_kernel(const float* __restrict__ qkv_w,
                                 const float* __restrict__ proj_w) {
    int i = (blockIdx.x * 256 + threadIdx.x) * 4;
    float4 v;
    __half2 h0, h1;
    if (i < 768 * 256) {
        v = *(const float4*)(qkv_w + i);
        h0 = __floats2half2_rn(v.x, v.y);
        h1 = __floats2half2_rn(v.z, v.w);
        *(__half2*)(g_wqkv + i)     = h0;
        *(__half2*)(g_wqkv + i + 2) = h1;
    } else {
        int k = i - 768 * 256;
        v = *(const float4*)(proj_w + k);
        h0 = __floats2half2_rn(v.x, v.y);
        h1 = __floats2half2_rn(v.z, v.w);
        *(__half2*)(g_wproj + k)     = h0;
        *(__half2*)(g_wproj + k + 2) = h1;
    }
}

// ============================================================
// GroupNorm, 3 phases (unchanged)
// ============================================================
__global__ void gn_partial_kernel(const float* __restrict__ x) {
    const float* xp = x + (size_t)blockIdx.x * 4096;
    int tid = threadIdx.x;
    float s = 0.f, ss = 0.f;
    #pragma unroll 8
    for (int i = tid * 4; i < 4096; i += 512) {
        float4 v = *(const float4*)(xp + i);
        s  += v.x + v.y + v.z + v.w;
        ss += v.x * v.x + v.y * v.y + v.z * v.z + v.w * v.w;
    }
    __shared__ float rs[128], rss[128];
    rs[tid] = s; rss[tid] = ss;
    __syncthreads();
    for (int o = 64; o > 0; o >>= 1) {
        if (tid < o) { rs[tid] += rs[tid + o]; rss[tid] += rss[tid + o]; }
        __syncthreads();
    }
    if (tid == 0) g_part[blockIdx.x] = make_float2(rs[0], rss[0]);
}

__global__ void gn_final_kernel() {
    int t = threadIdx.x;
    float s = 0.f, ss = 0.f;
    #pragma unroll
    for (int i = 0; i < 32; i++) { float2 p = g_part[t * 32 + i]; s += p.x; ss += p.y; }
    float mean = s / 131072.f;
    float var  = ss / 131072.f - mean * mean;
    g_stats[t] = make_float2(mean, rsqrtf(var + 1e-5f));
}

__global__ void gn_norm_kernel(const float* __restrict__ x,
                               const float* __restrict__ w,
                               const float* __restrict__ b) {
    __shared__ float tile[32][129];
    const int t0 = blockIdx.x * 128;
    const int bg = blockIdx.y;
    const int bb = bg >> 3, gg = bg & 7;
    const int tid = threadIdx.x;

    const float* xp = x + ((size_t)bb * 256 + gg * 32) * HWSZ + t0;
    #pragma unroll 4
    for (int i = tid; i < 1024; i += 256) {
        int row = i >> 5, c4 = i & 31;
        float4 v = *(const float4*)(xp + (size_t)row * HWSZ + c4 * 4);
        tile[row][c4 * 4 + 0] = v.x;
        tile[row][c4 * 4 + 1] = v.y;
        tile[row][c4 * 4 + 2] = v.z;
        tile[row][c4 * 4 + 3] = v.w;
    }
    float2 st = g_stats[bg];
    __syncthreads();

    const int tok = tid >> 1, seg = tid & 1;
    __half hv[16];
    #pragma unroll
    for (int i = 0; i < 16; i++) {
        int cc = seg * 16 + i;
        int c = gg * 32 + cc;
        float sc = st.y * w[c];
        float of = b[c] - st.x * sc;
        hv[i] = __float2half_rn(tile[cc][tok] * sc + of);
    }
    __half* dst = g_ht + ((size_t)bb * HWSZ + t0 + tok) * 256 + gg * 32 + seg * 16;
    *(uint4*)dst       = *(uint4*)hv;
    *(uint4*)(dst + 8) = *(uint4*)(hv + 8);
}

// ============================================================
// fp16 tensor-core GEMM (unchanged from R11).
// ============================================================
#define LDWH 20
#define TILEW (128 * LDWH)
#define GEMM_SMEM_BYTES (4 * TILEW * 4)
#define QSCALE 0.18033688011112042f
#define EPL 136

template<int M_TOTAL, bool QKV_MODE>
__global__ void __launch_bounds__(256, 2) gemm_h_kernel(
        const __half* __restrict__ A,
        const __half* __restrict__ Bt,
        const float* __restrict__ bias,
        const float* __restrict__ resid,
        float* __restrict__ out) {
    extern __shared__ uint32_t sw[];
    uint32_t* a_s = sw;
    uint32_t* b_s = sw + 2 * TILEW;
    const uint32_t a_u = smem_u32(a_s);
    const uint32_t b_u = smem_u32(b_s);

    const int tid = threadIdx.x, lane = tid & 31, wid = tid >> 5;
    const int g4 = lane >> 2, t4 = lane & 3;
    const int wm = wid >> 1, wn = wid & 1;
    const int bb = blockIdx.z;
    const int m0 = blockIdx.y * 128;
    const int n0 = blockIdx.x * 128;
    const __half* Bp = Bt + (size_t)bb * HWSZ * 256 + (size_t)n0 * 256;

    float acc[2][8][4];
    #pragma unroll
    for (int mt = 0; mt < 2; mt++)
        #pragma unroll
        for (int nt = 0; nt < 8; nt++)
            #pragma unroll
            for (int i = 0; i < 4; i++) acc[mt][nt][i] = 0.f;

    #pragma unroll 2
    for (int e = tid; e < 512; e += 256) {
        int r = e >> 2, c8 = e & 3;
        cp16(a_u + (r * LDWH + c8 * 4) * 4, A + (size_t)(m0 + r) * 256 + c8 * 8);
    }
    #pragma unroll 2
    for (int e = tid; e < 512; e += 256) {
        int r = e >> 2, c8 = e & 3;
        cp16(b_u + (r * LDWH + c8 * 4) * 4, Bp + (size_t)r * 256 + c8 * 8);
    }
    CP_COMMIT();

    for (int j = 0; j < 8; j++) {
        const int buf = j & 1;
        const uint32_t* at = a_s + buf * TILEW;
        const uint32_t* bt = b_s + buf * TILEW;

        CP_WAIT0();
        __syncthreads();

        if (j < 7) {
            const uint32_t ad = a_u + ((buf ^ 1) * TILEW) * 4;
            const uint32_t bd = b_u + ((buf ^ 1) * TILEW) * 4;
            const int k0 = (j + 1) * 32;
            #pragma unroll 2
            for (int e = tid; e < 512; e += 256) {
                int r = e >> 2, c8 = e & 3;
                cp16(ad + (r * LDWH + c8 * 4) * 4, A + (size_t)(m0 + r) * 256 + k0 + c8 * 8);
            }
            #pragma unroll 2
            for (int e = tid; e < 512; e += 256) {
                int r = e >> 2, c8 = e & 3;
                cp16(bd + (r * LDWH + c8 * 4) * 4, Bp + (size_t)r * 256 + k0 + c8 * 8);
            }
            CP_COMMIT();
        }

        #pragma unroll
        for (int kt = 0; kt < 2; kt++) {
            uint32_t af[2][4];
            #pragma unroll
            for (int mt = 0; mt < 2; mt++) {
                const uint32_t* ap = at + (wm * 32 + mt * 16 + g4) * LDWH + kt * 8 + t4;
                af[mt][0] = ap[0];
                af[mt][1] = ap[8 * LDWH];
                af[mt][2] = ap[4];
                af[mt][3] = ap[8 * LDWH + 4];
            }
            const uint32_t* bp = bt + (wn * 64 + g4) * LDWH + kt * 8 + t4;
            #pragma unroll
            for (int nt = 0; nt < 8; nt++) {
                uint32_t b0 = bp[nt * 8 * LDWH];
                uint32_t b1 = bp[nt * 8 * LDWH + 4];
                mma16(acc[0][nt], af[0], b0, b1);
                mma16(acc[1][nt], af[1], b0, b1);
            }
        }
        __syncthreads();
    }

    // ---- epilogue ----
    if (QKV_MODE) {
        uint16_t* ep = (uint16_t*)sw;
        const bool is_v = (m0 >= 512);
        const float sc = (m0 < 256) ? QSCALE : 1.0f;

        #pragma unroll
        for (int mt = 0; mt < 2; mt++) {
            const int r = wm * 32 + mt * 16 + g4;
            const float bv0 = bias[m0 + r], bv1 = bias[m0 + r + 8];
            #pragma unroll
            for (int nt = 0; nt < 8; nt++) {
                const int tl = wn * 64 + nt * 8 + 2 * t4;
                __half h0 = __float2half_rn((acc[mt][nt][0] + bv0) * sc);
                __half h1 = __float2half_rn((acc[mt][nt][1] + bv0) * sc);
                __half h2 = __float2half_rn((acc[mt][nt][2] + bv1) * sc);
                __half h3 = __float2half_rn((acc[mt][nt][3] + bv1) * sc);
                if (is_v) {
                    __half2 p01; p01.x = h0; p01.y = h1;
                    __half2 p23; p23.x = h2; p23.y = h3;
                    *(__half2*)&ep[(r)     * EPL + tl] = p01;
                    *(__half2*)&ep[(r + 8) * EPL + tl] = p23;
                } else {
                    ep[(tl)     * EPL + r]     = __half_as_ushort(h0);
                    ep[(tl + 1) * EPL + r]     = __half_as_ushort(h1);
                    ep[(tl)     * EPL + r + 8] = __half_as_ushort(h2);
                    ep[(tl + 1) * EPL + r + 8] = __half_as_ushort(h3);
                }
            }
        }
        __syncthreads();

        #pragma unroll
        for (int e = tid; e < 2048; e += 256) {
            const int a = e >> 4, c8 = e & 15;
            uint4 val = *(uint4*)&ep[a * EPL + c8 * 8];
            if (is_v) {
                const int ch = m0 - 512 + a;
                __half* gv = g_vh + ((size_t)(bb * 4 + (ch >> 6)) * 64 + (ch & 63)) * HWSZ
                           + n0 + c8 * 8;
                *(uint4*)gv = val;
            } else {
                const int gm = m0 + c8 * 8;
                const int tok = n0 + a;
                if (gm < 256) {
                    __half* gq = g_qh + ((size_t)(bb * 4 + (gm >> 6)) * HWSZ + tok) * 64
                               + (gm & 63);
                    *(uint4*)gq = val;
                } else {
                    __half* gk = g_kh + ((size_t)(bb * 4 + ((gm - 256) >> 6)) * HWSZ + tok) * 64
                               + (gm & 63);
                    *(uint4*)gk = val;
                }
            }
        }
    } else {
        #pragma unroll
        for (int mt = 0; mt < 2; mt++) {
            const int r0 = m0 + wm * 32 + mt * 16 + g4;
            const float bv0 = bias[r0], bv1 = bias[r0 + 8];
            #pragma unroll
            for (int nt = 0; nt < 8; nt++) {
                const int tok = n0 + wn * 64 + nt * 8 + 2 * t4;
                float v0 = acc[mt][nt][0] + bv0;
                float v1 = acc[mt][nt][1] + bv0;
                float v2 = acc[mt][nt][2] + bv1;
                float v3 = acc[mt][nt][3] + bv1;
                const float* rp = resid + ((size_t)bb * 256 + r0) * HWSZ + tok;
                float* op = out + ((size_t)bb * 256 + r0) * HWSZ + tok;
                float2 ra = *(const float2*)rp;
                float2 rb = *(const float2*)(rp + 8 * HWSZ);
                *(float2*)op              = make_float2(v0 + ra.x, v1 + ra.y);
                *(float2*)(op + 8 * HWSZ) = make_float2(v2 + rb.x, v3 + rb.y);
            }
        }
    }
}

// ============================================================
// fp16 flash attention: BM=256 query tile (8 warps x 32 rows),
// halves K/V L2 traffic vs BM=128. Per-warp structure = proven R10.
// ============================================================
#define LDW 36
#define KVW (64 * LDW)
#define ATTN_SMEM_BYTES (4 * KVW * 4)
#define ONE2 0x3C003C00u

__global__ void __launch_bounds__(256) attn_mma_kernel() {
    extern __shared__ uint32_t smw[];
    uint32_t* ks_base = smw;
    uint32_t* vs_base = smw + 2 * KVW;

    const int tid = threadIdx.x, lane = tid & 31, wid = tid >> 5;
    const int g4 = lane >> 2, t4 = lane & 3;
    const int bh = blockIdx.y;
    const int bb = bh >> 2, hh = bh & 3;
    const int i0 = blockIdx.x * 256;
    const int wrow = wid * 32;

    const __half* qg = g_qh + (size_t)bh * HWSZ * 64;
    const __half* kg = g_kh + (size_t)bh * HWSZ * 64;
    const __half* vg = g_vh + (size_t)bh * 64 * HWSZ;

    const uint32_t ks_u = smem_u32(ks_base);
    const uint32_t vs_u = smem_u32(vs_base);

    const int lm_m = lane >> 3;
    const uint32_t lm_row = (uint32_t)(((lm_m >> 1) * 8) + (lane & 7));
    const uint32_t lm_kb  = (uint32_t)((lm_m & 1) * 16);

    uint32_t qf[2][4][4];
    #pragma unroll
    for (int mt = 0; mt < 2; mt++) {
        const __half* qr0 = qg + (size_t)(i0 + wrow + mt * 16 + g4) * 64;
        const __half* qr1 = qr0 + 8 * 64;
        #pragma unroll
        for (int kt = 0; kt < 4; kt++) {
            qf[mt][kt][0] = *(const uint32_t*)(qr0 + kt * 16 + 2 * t4);
            qf[mt][kt][1] = *(const uint32_t*)(qr1 + kt * 16 + 2 * t4);
            qf[mt][kt][2] = *(const uint32_t*)(qr0 + kt * 16 + 2 * t4 + 8);
            qf[mt][kt][3] = *(const uint32_t*)(qr1 + kt * 16 + 2 * t4 + 8);
        }
    }

    float of[2][9][4];
    #pragma unroll
    for (int mt = 0; mt < 2; mt++)
        #pragma unroll
        for (int nt = 0; nt < 9; nt++)
            #pragma unroll
            for (int i = 0; i < 4; i++) of[mt][nt][i] = 0.f;

    #pragma unroll 2
    for (int e = tid; e < 512; e += 256) {
        int r = e >> 3, c = e & 7;
        cp16(ks_u + (r * LDW) * 4 + c * 16, kg + (size_t)r * 64 + c * 8);
    }
    #pragma unroll 2
    for (int e = tid; e < 512; e += 256) {
        int r = e >> 3, c = e & 7;
        cp16(vs_u + (r * LDW) * 4 + c * 16, vg + (size_t)r * HWSZ + c * 8);
    }
    CP_COMMIT();

    for (int j = 0; j < 64; j++) {
        const int buf = j & 1;
        const uint32_t klm = ks_u + (buf * KVW + lm_row * LDW) * 4 + lm_kb;
        const uint32_t vlm = vs_u + (buf * KVW + lm_row * LDW) * 4 + lm_kb;

        CP_WAIT0();
        __syncthreads();

        if (j < 63) {
            const uint32_t kd = ks_u + ((buf ^ 1) * KVW) * 4;
            const uint32_t vd = vs_u + ((buf ^ 1) * KVW) * 4;
            const __half* kn = kg + (size_t)(j + 1) * 64 * 64;
            const __half* vn = vg + (j + 1) * 64;
            #pragma unroll 2
            for (int e = tid; e < 512; e += 256) {
                int r = e >> 3, c = e & 7;
                cp16(kd + (r * LDW) * 4 + c * 16, kn + (size_t)r * 64 + c * 8);
            }
            #pragma unroll 2
            for (int e = tid; e < 512; e += 256) {
                int r = e >> 3, c = e & 7;
                cp16(vd + (r * LDW) * 4 + c * 16, vn + (size_t)r * HWSZ + c * 8);
            }
            CP_COMMIT();
        }

        float sf[2][8][4];
        #pragma unroll
        for (int mt = 0; mt < 2; mt++)
            #pragma unroll
            for (int nt = 0; nt < 8; nt++)
                #pragma unroll
                for (int i = 0; i < 4; i++) sf[mt][nt][i] = 0.f;

        // ---- S_A: keys 0..31 ----
        #pragma unroll
        for (int kt = 0; kt < 4; kt++) {
            #pragma unroll
            for (int ntp = 0; ntp < 2; ntp++) {
                uint32_t br[4];
                ldsm4(br, klm + (ntp * 16 * LDW) * 4 + kt * 32);
                mma16(sf[0][2 * ntp],     qf[0][kt], br[0], br[1]);
                mma16(sf[1][2 * ntp],     qf[1][kt], br[0], br[1]);
                mma16(sf[0][2 * ntp + 1], qf[0][kt], br[2], br[3]);
                mma16(sf[1][2 * ntp + 1], qf[1][kt], br[2], br[3]);
            }
        }

        uint32_t pa[2][4][4];

        // ---- S_B || ex2_A ----
        #pragma unroll
        for (int kt = 0; kt < 4; kt++) {
            #pragma unroll
            for (int ntp = 2; ntp < 4; ntp++) {
                uint32_t br[4];
                ldsm4(br, klm + (ntp * 16 * LDW) * 4 + kt * 32);
                mma16(sf[0][2 * ntp],     qf[0][kt], br[0], br[1]);
                mma16(sf[1][2 * ntp],     qf[1][kt], br[0], br[1]);
                mma16(sf[0][2 * ntp + 1], qf[0][kt], br[2], br[3]);
                mma16(sf[1][2 * ntp + 1], qf[1][kt], br[2], br[3]);
            }
        }
        #pragma unroll
        for (int mt = 0; mt < 2; mt++)
            #pragma unroll
            for (int nt = 0; nt < 4; nt++) {
                float p0 = ex2f(sf[mt][nt][0]);
                float p1 = ex2f(sf[mt][nt][1]);
                float p2 = ex2f(sf[mt][nt][2]);
                float p3 = ex2f(sf[mt][nt][3]);
                pa[mt][nt >> 1][(nt & 1) * 2]     = pack_h2(p0, p1);
                pa[mt][nt >> 1][(nt & 1) * 2 + 1] = pack_h2(p2, p3);
            }

        // ---- PV_A || ex2_B ----
        #pragma unroll
        for (int kt = 0; kt < 2; kt++) {
            #pragma unroll
            for (int ntp = 0; ntp < 4; ntp++) {
                uint32_t br[4];
                ldsm4(br, vlm + (ntp * 16 * LDW) * 4 + kt * 32);
                mma16(of[0][2 * ntp],     pa[0][kt], br[0], br[1]);
                mma16(of[1][2 * ntp],     pa[1][kt], br[0], br[1]);
                mma16(of[0][2 * ntp + 1], pa[0][kt], br[2], br[3]);
                mma16(of[1][2 * ntp + 1], pa[1][kt], br[2], br[3]);
            }
            mma16(of[0][8], pa[0][kt], ONE2, ONE2);
            mma16(of[1][8], pa[1][kt], ONE2, ONE2);
        }
        #pragma unroll
        for (int mt = 0; mt < 2; mt++)
            #pragma unroll
            for (int nt = 4; nt < 8; nt++) {
                float p0 = ex2f(sf[mt][nt][0]);
                float p1 = ex2f(sf[mt][nt][1]);
                float p2 = ex2f(sf[mt][nt][2]);
                float p3 = ex2f(sf[mt][nt][3]);
                pa[mt][nt >> 1][(nt & 1) * 2]     = pack_h2(p0, p1);
                pa[mt][nt >> 1][(nt & 1) * 2 + 1] = pack_h2(p2, p3);
            }

        // ---- PV_B ----
        #pragma unroll
        for (int kt = 2; kt < 4; kt++) {
            #pragma unroll
            for (int ntp = 0; ntp < 4; ntp++) {
                uint32_t br[4];
                ldsm4(br, vlm + (ntp * 16 * LDW) * 4 + kt * 32);
                mma16(of[0][2 * ntp],     pa[0][kt], br[0], br[1]);
                mma16(of[1][2 * ntp],     pa[1][kt], br[0], br[1]);
                mma16(of[0][2 * ntp + 1], pa[0][kt], br[2], br[3]);
                mma16(of[1][2 * ntp + 1], pa[1][kt], br[2], br[3]);
            }
            mma16(of[0][8], pa[0][kt], ONE2, ONE2);
            mma16(of[1][8], pa[1][kt], ONE2, ONE2);
        }
    }

    #pragma unroll
    for (int mt = 0; mt < 2; mt++) {
        float inv0 = 1.f / of[mt][8][0];
        float inv1 = 1.f / of[mt][8][2];
        int tok = i0 + wrow + mt * 16 + g4;
        __half* d0 = g_oh + ((size_t)bb * HWSZ + tok) * 256 + hh * 64;
        __half* d1 = d0 + 8 * 256;
        #pragma unroll
        for (int nt = 0; nt < 8; nt++) {
            int ch = nt * 8 + 2 * t4;
            *(__half2*)(d0 + ch) = __floats2half2_rn(of[mt][nt][0] * inv0,
                                                     of[mt][nt][1] * inv0);
            *(__half2*)(d1 + ch) = __floats2half2_rn(of[mt][nt][2] * inv1,
                                                     of[mt][nt][3] * inv1);
        }
    }
}

// ============================================================
extern "C" void kernel_launch(void* const* d_in, const int* in_sizes, int n_in,
                              void* d_out, int out_size) {
    const float* x      = (const float*)d_in[0];
    const float* norm_w = (const float*)d_in[1];
    const float* norm_b = (const float*)d_in[2];
    const float* qkv_w  = (const float*)d_in[3];
    const float* qkv_b  = (const float*)d_in[4];
    const float* proj_w = (const float*)d_in[5];
    const float* proj_b = (const float*)d_in[6];
    float* out = (float*)d_out;

    void *pht, *poh, *pwq, *pwp;
    cudaGetSymbolAddress(&pht, g_ht);
    cudaGetSymbolAddress(&poh, g_oh);
    cudaGetSymbolAddress(&pwq, g_wqkv);
    cudaGetSymbolAddress(&pwp, g_wproj);

    cudaFuncSetAttribute(gemm_h_kernel<768, true>,
                         cudaFuncAttributeMaxDynamicSharedMemorySize, GEMM_SMEM_BYTES);
    cudaFuncSetAttribute(gemm_h_kernel<256, false>,
                         cudaFuncAttributeMaxDynamicSharedMemorySize, GEMM_SMEM_BYTES);
    cudaFuncSetAttribute(attn_mma_kernel,
                         cudaFuncAttributeMaxDynamicSharedMemorySize, ATTN_SMEM_BYTES);

    convert_w_kernel<<<320, 256>>>(qkv_w, proj_w);
    gn_partial_kernel<<<1024, 128>>>(x);
    gn_final_kernel<<<1, 32>>>();
    gn_norm_kernel<<<dim3(HWSZ / 128, 32), 256>>>(x, norm_w, norm_b);

    gemm_h_kernel<768, true><<<dim3(HWSZ / 128, 768 / 128, BATCH), 256, GEMM_SMEM_BYTES>>>(
        (const __half*)pwq, (const __half*)pht, qkv_b, nullptr, nullptr);

    attn_mma_kernel<<<dim3(HWSZ / 256, NBH), 256, ATTN_SMEM_BYTES>>>();

    gemm_h_kernel<256, false><<<dim3(HWSZ / 128, 256 / 128, BATCH), 256, GEMM_SMEM_BYTES>>>(
        (const __half*)pwp, (const __half*)poh, proj_b, x, out);
}